// round 6
// baseline (speedup 1.0000x reference)
#include <cuda_runtime.h>

#define BS 2
#define NPTS 65536
#define KNN 16
#define CH 16
#define CO 32
#define NK (BS*NPTS*KNN)
#define NP (BS*NPTS)
#define EPSV 1e-5f
#define SLOPE 0.2f

// ---------------- scratch (same footprint as the R1 binary that passed) ----------------
__device__ float4 g_xyzT[NP];            // [b*N+n] = {x,y,z,0}
__device__ float  g_featT[NP*CH];        // [b*N+n][16]
__device__ float  g_z1[NP*CH];           // stage1 pre-BN pooled output
__device__ float  g_z2[NP*CO];           // stage2 pre-BN pooled output
__device__ float  g_acc[192];            // stat sums
__device__ float  g_bnp[192];            // finalized BN scale/shift

typedef unsigned long long u64;

__device__ __forceinline__ u64 pack2(float lo, float hi){
    u64 r; asm("mov.b64 %0, {%1,%2};" : "=l"(r) : "f"(lo), "f"(hi)); return r;
}
__device__ __forceinline__ void fma2(u64 &d, u64 a, u64 b){
    asm("fma.rn.f32x2 %0, %1, %2, %3;" : "=l"(d) : "l"(a), "l"(b), "l"(d));
}
__device__ __forceinline__ float lohi_sum(u64 v){
    float lo, hi; asm("mov.b64 {%0,%1}, %2;" : "=f"(lo), "=f"(hi) : "l"(v)); return lo + hi;
}
__device__ __forceinline__ float lrelu(float x){ return x >= 0.f ? x : SLOPE * x; }
__device__ __forceinline__ float wsum(float v){
    #pragma unroll
    for (int o = 16; o; o >>= 1) v += __shfl_down_sync(0xffffffffu, v, o);
    return v;
}

// ---------------- transpose xyz + feature, zero accumulators ----------------
__global__ void k_t01(const float* __restrict__ xyz, const float* __restrict__ feat){
    int i = blockIdx.x * blockDim.x + threadIdx.x;   // grid exactly covers NP
    if (blockIdx.x == 0 && threadIdx.x < 192) g_acc[threadIdx.x] = 0.f;
    int b = i >> 16, n = i & 65535;
    const float* xp = xyz + b * 3 * NPTS;
    g_xyzT[i] = make_float4(xp[n], xp[NPTS + n], xp[2 * NPTS + n], 0.f);
    const float* fp = feat + b * CH * NPTS;
    #pragma unroll
    for (int c = 0; c < CH; c++) g_featT[i * CH + c] = fp[c * NPTS + n];
}

// ---------------- per-edge raw moments for exact BN1 stats ----------------
// A layout (sums over all NK edges):
//  0:dis 1:dis^2 2-4:dis*c 5-7:dis*n 8-10:c 11-13:n
//  14-19:c⊗c(sym6) 20-25:n⊗n(sym6) 26-34:n_i*c_j (i*3+j)
__global__ void __launch_bounds__(256) k_stats1e(const int* __restrict__ nidx){
    float A[35];
    #pragma unroll
    for (int i = 0; i < 35; i++) A[i] = 0.f;
    int t = threadIdx.x;
    int T = gridDim.x * blockDim.x;
    for (int e = blockIdx.x * blockDim.x + t; e < NK; e += T){
        int id = nidx[e];
        int p = e >> 4, b = e >> 20;
        float4 cc = g_xyzT[p];
        float4 nb = g_xyzT[(b << 16) + id];
        float rx = cc.x - nb.x, ry = cc.y - nb.y, rz = cc.z - nb.z;
        float dis = sqrtf(rx*rx + ry*ry + rz*rz);
        A[0] += dis;       A[1] += dis*dis;
        A[2] += dis*cc.x;  A[3] += dis*cc.y;  A[4] += dis*cc.z;
        A[5] += dis*nb.x;  A[6] += dis*nb.y;  A[7] += dis*nb.z;
        A[8] += cc.x;  A[9] += cc.y;  A[10] += cc.z;
        A[11] += nb.x; A[12] += nb.y; A[13] += nb.z;
        A[14] += cc.x*cc.x; A[15] += cc.x*cc.y; A[16] += cc.x*cc.z;
        A[17] += cc.y*cc.y; A[18] += cc.y*cc.z; A[19] += cc.z*cc.z;
        A[20] += nb.x*nb.x; A[21] += nb.x*nb.y; A[22] += nb.x*nb.z;
        A[23] += nb.y*nb.y; A[24] += nb.y*nb.z; A[25] += nb.z*nb.z;
        A[26] += nb.x*cc.x; A[27] += nb.x*cc.y; A[28] += nb.x*cc.z;
        A[29] += nb.y*cc.x; A[30] += nb.y*cc.y; A[31] += nb.y*cc.z;
        A[32] += nb.z*cc.x; A[33] += nb.z*cc.y; A[34] += nb.z*cc.z;
    }
    __shared__ float red[35];
    if (t < 35) red[t] = 0.f;
    __syncthreads();
    int lane = t & 31;
    #pragma unroll
    for (int i = 0; i < 35; i++){
        float v = wsum(A[i]);
        if (lane == 0) atomicAdd(&red[i], v);
    }
    __syncthreads();
    if (t < 35) atomicAdd(&g_acc[t], red[t]);
}

__device__ __forceinline__ int s6(int i, int j){
    if (i > j){ int x = i; i = j; j = x; }
    return i * 3 - ((i * (i + 1)) >> 1) + j;
}

// ---------------- finalize BN1 from moments ----------------
__global__ void k_fin1(const float* __restrict__ w1, const float* __restrict__ b1,
                       const float* __restrict__ g, const float* __restrict__ be){
    __shared__ float S10[10], M10[100];
    int t = threadIdx.x;
    if (t == 0){
        float A[35];
        for (int i = 0; i < 35; i++) A[i] = g_acc[i];
        const float* Adc = A + 2; const float* Adn = A + 5;
        const float* Ac  = A + 8; const float* An  = A + 11;
        const float* Acc = A + 14; const float* Ann = A + 20; const float* Anc = A + 26;
        S10[0] = A[0];
        for (int i = 0; i < 3; i++){
            S10[1+i] = Ac[i] - An[i]; S10[4+i] = Ac[i]; S10[7+i] = An[i];
        }
        float M[10][10];
        M[0][0] = A[1];
        for (int i = 0; i < 3; i++){
            M[0][1+i] = Adc[i] - Adn[i];
            M[0][4+i] = Adc[i];
            M[0][7+i] = Adn[i];
        }
        for (int i = 0; i < 3; i++) for (int j = 0; j < 3; j++){
            float cc = Acc[s6(i,j)], nn = Ann[s6(i,j)];
            float nicj = Anc[i*3+j];   // sum n_i c_j
            float njci = Anc[j*3+i];   // sum c_i n_j
            M[1+i][1+j] = cc - nicj - njci + nn;
            M[1+i][4+j] = cc - nicj;
            M[1+i][7+j] = njci - nn;
            M[4+i][4+j] = cc;
            M[4+i][7+j] = njci;
            M[7+i][7+j] = nn;
        }
        for (int i = 0; i < 10; i++) for (int j = 0; j < i; j++) M[i][j] = M[j][i];
        for (int i = 0; i < 10; i++) for (int j = 0; j < 10; j++) M10[i*10+j] = M[i][j];
    }
    __syncthreads();
    if (t < 16){
        float w[10];
        #pragma unroll
        for (int j = 0; j < 10; j++) w[j] = w1[t*10+j];
        float b = b1[t];
        float sw = 0.f;
        #pragma unroll
        for (int j = 0; j < 10; j++) sw += w[j] * S10[j];
        float q = 0.f;
        for (int i = 0; i < 10; i++){
            float wi = w[i];
            for (int j = 0; j < 10; j++) q += wi * w[j] * M10[i*10+j];
        }
        const float inv = 1.f / (float)NK;
        float mean = sw * inv + b;
        float ey2 = (q + 2.f * b * sw) * inv + b * b;
        float var = ey2 - mean * mean;
        float sc = g[t] * rsqrtf(var + EPSV);
        g_bnp[t] = sc;
        g_bnp[16 + t] = be[t] - mean * sc;
    }
}

// ---------------- stage 1: pool1 + y2 stats (no store) + z1 stats ----------------
__global__ void __launch_bounds__(256) k_stage1(
        const int* __restrict__ nidx, const float* __restrict__ w1, const float* __restrict__ b1,
        const float* __restrict__ w2, const float* __restrict__ b2,
        const float* __restrict__ wfc, const float* __restrict__ bfc,
        const float* __restrict__ wap, const float* __restrict__ bap){
    __shared__ float W1s[160], b1s[16], sc1[16], sh1[16], b2s[16], WapT[32*16], baps[16];
    __shared__ __align__(16) float fS[8][16][32];
    __shared__ __align__(16) float aggS[8][32];
    __shared__ float red[64];
    int t = threadIdx.x;
    if (t < 160) W1s[t] = w1[t];
    if (t < 16){ b1s[t]=b1[t]; b2s[t]=b2[t]; sc1[t]=g_bnp[t]; sh1[t]=g_bnp[16+t]; baps[t]=bap[t]; }
    for (int i = t; i < 512; i += 256){ int o = i >> 5, c = i & 31; WapT[c * 16 + o] = wap[i]; }
    __syncthreads();
    int lane = t & 31, w = t >> 5, c2 = lane - 16;
    u64 wr2[16];
    #pragma unroll
    for (int j = 0; j < 16; j++) wr2[j] = pack2(wfc[lane * 32 + 2*j], wfc[lane * 32 + 2*j + 1]);
    float bfcl = bfc[lane];
    u64 w2r2[8];
    #pragma unroll
    for (int j = 0; j < 8; j++)
        w2r2[j] = (lane >= 16) ? pack2(w2[c2 * 16 + 2*j], w2[c2 * 16 + 2*j + 1]) : 0ULL;
    float sA = 0.f, ssA = 0.f;
    int warpsTotal = (gridDim.x * blockDim.x) >> 5;
    for (int pid = blockIdx.x * 8 + w; pid < NP; pid += warpsTotal){
        int b = pid >> 16;
        int idxl = (lane < 16) ? nidx[pid * 16 + lane] : 0;
        float4 cc = g_xyzT[pid];
        float f[16];
        #pragma unroll
        for (int k = 0; k < 16; k++){
            int id = __shfl_sync(0xffffffffu, idxl, k);
            float v;
            if (lane < 16){
                v = g_featT[((b << 16) + id) * CH + lane];
            } else {
                float4 nb = g_xyzT[(b << 16) + id];
                float rx = cc.x - nb.x, ry = cc.y - nb.y, rz = cc.z - nb.z;
                float dis = sqrtf(rx*rx + ry*ry + rz*rz);
                const float* wp = W1s + c2 * 10;
                float y = b1s[c2] + wp[0]*dis + wp[1]*rx + wp[2]*ry + wp[3]*rz
                        + wp[4]*cc.x + wp[5]*cc.y + wp[6]*cc.z + wp[7]*nb.x + wp[8]*nb.y + wp[9]*nb.z;
                v = lrelu(y * sc1[c2] + sh1[c2]);
            }
            f[k] = v;
            fS[w][k][lane] = v;
        }
        __syncwarp();
        float att[16];
        #pragma unroll
        for (int k = 0; k < 16; k++){
            const ulonglong2* fp = reinterpret_cast<const ulonglong2*>(&fS[w][k][0]);
            u64 acc = 0ULL;
            #pragma unroll
            for (int i = 0; i < 8; i++){
                ulonglong2 u = fp[i];
                fma2(acc, u.x, wr2[2*i]);
                fma2(acc, u.y, wr2[2*i + 1]);
            }
            att[k] = lohi_sum(acc) + bfcl;
        }
        float m = att[0];
        #pragma unroll
        for (int k = 1; k < 16; k++) m = fmaxf(m, att[k]);
        float s = 0.f, agg = 0.f;
        #pragma unroll
        for (int k = 0; k < 16; k++){ float e = __expf(att[k] - m); s += e; agg += f[k] * e; }
        agg /= s;
        aggS[w][lane] = agg;
        __syncwarp();
        if (lane < 16){
            float z = baps[lane];
            #pragma unroll
            for (int c = 0; c < 32; c++) z += WapT[c * 16 + lane] * aggS[w][c];
            g_z1[pid * CH + lane] = z;
            sA += z; ssA += z * z;
        } else {
            // y2 = W2 @ fx1 + b2 per edge — stats only, no store
            #pragma unroll
            for (int k = 0; k < 16; k++){
                const ulonglong2* xp = reinterpret_cast<const ulonglong2*>(&fS[w][k][16]);
                u64 acc = 0ULL;
                #pragma unroll
                for (int i = 0; i < 4; i++){
                    ulonglong2 u = xp[i];
                    fma2(acc, u.x, w2r2[2*i]);
                    fma2(acc, u.y, w2r2[2*i + 1]);
                }
                float y2 = lohi_sum(acc) + b2s[c2];
                sA += y2; ssA += y2 * y2;
            }
        }
        __syncwarp();
    }
    // epilogue: block-reduce fused stats
    if (t < 64) red[t] = 0.f;
    __syncthreads();
    atomicAdd(&red[lane], sA);
    atomicAdd(&red[32 + lane], ssA);
    __syncthreads();
    if (t < 32){
        int off = (t < 16) ? (96 + t) : (48 + t);   // z1 stats @96/112, y2 stats @64/80
        atomicAdd(&g_acc[off], red[t]);
        atomicAdd(&g_acc[off + 16], red[32 + t]);
    }
}

// ---------------- finalize BN2 (count NK) + BN ap1 (count NP) ----------------
__global__ void k_fin2AB(const float* __restrict__ g2, const float* __restrict__ be2,
                         const float* __restrict__ gA, const float* __restrict__ beA){
    int t = threadIdx.x;
    if (t < 16){
        float inv = 1.f / (float)NK;
        float m = g_acc[64 + t] * inv;
        float v = g_acc[80 + t] * inv - m * m;
        float sc = g2[t] * rsqrtf(v + EPSV);
        g_bnp[32 + t] = sc;
        g_bnp[48 + t] = be2[t] - m * sc;
    } else if (t < 32){
        int c = t - 16;
        float inv = 1.f / (float)NP;
        float m = g_acc[96 + c] * inv;
        float v = g_acc[112 + c] * inv - m * m;
        float sc = gA[c] * rsqrtf(v + EPSV);
        g_bnp[64 + c] = sc;
        g_bnp[80 + c] = beA[c] - m * sc;
    }
}

// ---------------- stage 2: recompute fx1/y2, pool2, fused z2 stats ----------------
__global__ void __launch_bounds__(256) k_stage2(
        const int* __restrict__ nidx, const float* __restrict__ w1, const float* __restrict__ b1,
        const float* __restrict__ w2, const float* __restrict__ b2,
        const float* __restrict__ wfc, const float* __restrict__ bfc,
        const float* __restrict__ wap, const float* __restrict__ bap){
    __shared__ float W1s[160], b1s[16], sc1[16], sh1[16], sc2[16], sh2[16],
                     scA[16], shA[16], b2s[16], WapT[32*32], baps[32];
    __shared__ __align__(16) float fS[8][16][32];
    __shared__ __align__(16) float fx1S[8][16][16];
    __shared__ __align__(16) float aggS[8][32];
    __shared__ float red[64];
    int t = threadIdx.x;
    if (t < 160) W1s[t] = w1[t];
    if (t < 16){
        b1s[t]=b1[t]; b2s[t]=b2[t];
        sc1[t]=g_bnp[t];    sh1[t]=g_bnp[16+t];
        sc2[t]=g_bnp[32+t]; sh2[t]=g_bnp[48+t];
        scA[t]=g_bnp[64+t]; shA[t]=g_bnp[80+t];
    }
    if (t < 32) baps[t] = bap[t];
    for (int i = t; i < 1024; i += 256){ int o = i >> 5, c = i & 31; WapT[c * 32 + o] = wap[i]; }
    __syncthreads();
    int lane = t & 31, w = t >> 5, c2 = lane - 16;
    u64 wr2[16];
    #pragma unroll
    for (int j = 0; j < 16; j++) wr2[j] = pack2(wfc[lane * 32 + 2*j], wfc[lane * 32 + 2*j + 1]);
    float bfcl = bfc[lane];
    u64 w2r2[8];
    #pragma unroll
    for (int j = 0; j < 8; j++)
        w2r2[j] = (lane >= 16) ? pack2(w2[c2 * 16 + 2*j], w2[c2 * 16 + 2*j + 1]) : 0ULL;
    float sA = 0.f, ssA = 0.f;
    int warpsTotal = (gridDim.x * blockDim.x) >> 5;
    for (int pid = blockIdx.x * 8 + w; pid < NP; pid += warpsTotal){
        int b = pid >> 16;
        int idxl = (lane < 16) ? nidx[pid * 16 + lane] : 0;
        float4 cc = g_xyzT[pid];
        float f[16];
        #pragma unroll
        for (int k = 0; k < 16; k++){
            int id = __shfl_sync(0xffffffffu, idxl, k);
            if (lane < 16){
                float v = g_z1[((b << 16) + id) * CH + lane];
                v = v * scA[lane] + shA[lane];
                f[k] = lrelu(v);
            } else {
                float4 nb = g_xyzT[(b << 16) + id];
                float rx = cc.x - nb.x, ry = cc.y - nb.y, rz = cc.z - nb.z;
                float dis = sqrtf(rx*rx + ry*ry + rz*rz);
                const float* wp = W1s + c2 * 10;
                float y = b1s[c2] + wp[0]*dis + wp[1]*rx + wp[2]*ry + wp[3]*rz
                        + wp[4]*cc.x + wp[5]*cc.y + wp[6]*cc.z + wp[7]*nb.x + wp[8]*nb.y + wp[9]*nb.z;
                fx1S[w][k][c2] = lrelu(y * sc1[c2] + sh1[c2]);
            }
        }
        __syncwarp();
        if (lane >= 16){
            #pragma unroll
            for (int k = 0; k < 16; k++){
                const ulonglong2* xp = reinterpret_cast<const ulonglong2*>(&fx1S[w][k][0]);
                u64 acc = 0ULL;
                #pragma unroll
                for (int i = 0; i < 4; i++){
                    ulonglong2 u = xp[i];
                    fma2(acc, u.x, w2r2[2*i]);
                    fma2(acc, u.y, w2r2[2*i + 1]);
                }
                float y2 = lohi_sum(acc) + b2s[c2];
                f[k] = lrelu(y2 * sc2[c2] + sh2[c2]);
            }
        }
        #pragma unroll
        for (int k = 0; k < 16; k++) fS[w][k][lane] = f[k];
        __syncwarp();
        float att[16];
        #pragma unroll
        for (int k = 0; k < 16; k++){
            const ulonglong2* fp = reinterpret_cast<const ulonglong2*>(&fS[w][k][0]);
            u64 acc = 0ULL;
            #pragma unroll
            for (int i = 0; i < 8; i++){
                ulonglong2 u = fp[i];
                fma2(acc, u.x, wr2[2*i]);
                fma2(acc, u.y, wr2[2*i + 1]);
            }
            att[k] = lohi_sum(acc) + bfcl;
        }
        float m = att[0];
        #pragma unroll
        for (int k = 1; k < 16; k++) m = fmaxf(m, att[k]);
        float s = 0.f, agg = 0.f;
        #pragma unroll
        for (int k = 0; k < 16; k++){ float e = __expf(att[k] - m); s += e; agg += f[k] * e; }
        agg /= s;
        aggS[w][lane] = agg;
        __syncwarp();
        float z = baps[lane];
        #pragma unroll
        for (int c = 0; c < 32; c++) z += WapT[c * 32 + lane] * aggS[w][c];
        g_z2[pid * CO + lane] = z;
        sA += z; ssA += z * z;
        __syncwarp();
    }
    if (t < 64) red[t] = 0.f;
    __syncthreads();
    atomicAdd(&red[lane], sA);
    atomicAdd(&red[32 + lane], ssA);
    __syncthreads();
    if (t < 32){
        atomicAdd(&g_acc[128 + t], red[t]);
        atomicAdd(&g_acc[160 + t], red[32 + t]);
    }
}

// ---------------- finalize BN ap2 ----------------
__global__ void k_finB(const float* __restrict__ g, const float* __restrict__ be){
    int t = threadIdx.x;
    if (t < 32){
        float inv = 1.f / (float)NP;
        float m = g_acc[128 + t] * inv;
        float v = g_acc[160 + t] * inv - m * m;
        float sc = g[t] * rsqrtf(v + EPSV);
        g_bnp[96 + t] = sc;
        g_bnp[128 + t] = be[t] - m * sc;
    }
}

// ---------------- final BN+LReLU + transpose to output layout ----------------
__global__ void k_out(float* __restrict__ out){
    __shared__ float tile[32][33];
    int bx = blockIdx.x;
    int b = bx >> 11;
    int n0 = (bx & 2047) << 5;
    int tx = threadIdx.x, ty = threadIdx.y;
    #pragma unroll
    for (int i = 0; i < 4; i++){
        int r = ty + i * 8;
        tile[r][tx] = g_z2[((b << 16) + n0 + r) * CO + tx];
    }
    __syncthreads();
    #pragma unroll
    for (int i = 0; i < 4; i++){
        int c = ty + i * 8;
        float v = tile[tx][c] * g_bnp[96 + c] + g_bnp[128 + c];
        out[(b * CO + c) * NPTS + n0 + tx] = lrelu(v);
    }
}

extern "C" void kernel_launch(void* const* d_in, const int* in_sizes, int n_in,
                              void* d_out, int out_size){
    const float* xyz     = (const float*)d_in[0];
    const float* feature = (const float*)d_in[1];
    const int*   nidx    = (const int*)  d_in[2];
    const float* w_mlp1  = (const float*)d_in[3];
    const float* b_mlp1  = (const float*)d_in[4];
    const float* g_mlp1  = (const float*)d_in[5];
    const float* be_mlp1 = (const float*)d_in[6];
    const float* w_fc1   = (const float*)d_in[7];
    const float* b_fc1   = (const float*)d_in[8];
    const float* w_ap1   = (const float*)d_in[9];
    const float* b_ap1   = (const float*)d_in[10];
    const float* g_ap1   = (const float*)d_in[11];
    const float* be_ap1  = (const float*)d_in[12];
    const float* w_mlp2  = (const float*)d_in[13];
    const float* b_mlp2  = (const float*)d_in[14];
    const float* g_mlp2  = (const float*)d_in[15];
    const float* be_mlp2 = (const float*)d_in[16];
    const float* w_fc2   = (const float*)d_in[17];
    const float* b_fc2   = (const float*)d_in[18];
    const float* w_ap2   = (const float*)d_in[19];
    const float* b_ap2   = (const float*)d_in[20];
    const float* g_ap2   = (const float*)d_in[21];
    const float* be_ap2  = (const float*)d_in[22];
    float* out = (float*)d_out;

    k_t01<<<512, 256>>>(xyz, feature);
    k_stats1e<<<512, 256>>>(nidx);
    k_fin1<<<1, 32>>>(w_mlp1, b_mlp1, g_mlp1, be_mlp1);
    k_stage1<<<1024, 256>>>(nidx, w_mlp1, b_mlp1, w_mlp2, b_mlp2, w_fc1, b_fc1, w_ap1, b_ap1);
    k_fin2AB<<<1, 32>>>(g_mlp2, be_mlp2, g_ap1, be_ap1);
    k_stage2<<<1024, 256>>>(nidx, w_mlp1, b_mlp1, w_mlp2, b_mlp2, w_fc2, b_fc2, w_ap2, b_ap2);
    k_finB<<<1, 32>>>(g_ap2, be_ap2);
    dim3 bt(32, 8);
    k_out<<<4096, bt>>>(out);
}

// round 7
// speedup vs baseline: 1.9364x; 1.9364x over previous
#include <cuda_runtime.h>

#define BS 2
#define NPTS 65536
#define KNN 16
#define CH 16
#define CO 32
#define NK (BS*NPTS*KNN)
#define NP (BS*NPTS)
#define EPSV 1e-5f
#define SLOPE 0.2f

// ---------------- scratch ----------------
__device__ float4 g_xyzT[NP];            // [b*N+n] = {x,y,z,0}
__device__ float  g_featT[NP*CH];        // [b*N+n][16]
__device__ float  g_z1[NP*CH];           // stage1 pre-BN pooled output
__device__ float  g_z2[NP*CO];           // stage2 pre-BN pooled output
__device__ float  g_acc[192];            // stat sums
__device__ float  g_bnp[192];            // finalized BN scale/shift

typedef unsigned long long u64;

__device__ __forceinline__ u64 pack2(float lo, float hi){
    u64 r; asm("mov.b64 %0, {%1,%2};" : "=l"(r) : "f"(lo), "f"(hi)); return r;
}
__device__ __forceinline__ void fma2(u64 &d, u64 a, u64 b){
    asm("fma.rn.f32x2 %0, %1, %2, %3;" : "=l"(d) : "l"(a), "l"(b), "l"(d));
}
__device__ __forceinline__ float lohi_sum(u64 v){
    float lo, hi; asm("mov.b64 {%0,%1}, %2;" : "=f"(lo), "=f"(hi) : "l"(v)); return lo + hi;
}
__device__ __forceinline__ float lrelu(float x){ return x >= 0.f ? x : SLOPE * x; }
__device__ __forceinline__ float wsum(float v){
    #pragma unroll
    for (int o = 16; o; o >>= 1) v += __shfl_down_sync(0xffffffffu, v, o);
    return v;
}

// ---------------- transpose xyz + feature, zero accumulators ----------------
__global__ void k_t01(const float* __restrict__ xyz, const float* __restrict__ feat){
    int i = blockIdx.x * blockDim.x + threadIdx.x;   // grid exactly covers NP
    if (blockIdx.x == 0 && threadIdx.x < 192) g_acc[threadIdx.x] = 0.f;
    int b = i >> 16, n = i & 65535;
    const float* xp = xyz + b * 3 * NPTS;
    g_xyzT[i] = make_float4(xp[n], xp[NPTS + n], xp[2 * NPTS + n], 0.f);
    const float* fp = feat + b * CH * NPTS + n;
    float4* dst = reinterpret_cast<float4*>(&g_featT[i * CH]);
    #pragma unroll
    for (int q = 0; q < 4; q++){
        float4 v;
        v.x = fp[(4*q + 0) * NPTS];
        v.y = fp[(4*q + 1) * NPTS];
        v.z = fp[(4*q + 2) * NPTS];
        v.w = fp[(4*q + 3) * NPTS];
        dst[q] = v;
    }
}

// ---------------- per-edge raw moments for exact BN1 stats ----------------
__global__ void __launch_bounds__(256) k_stats1e(const int* __restrict__ nidx){
    float A[35];
    #pragma unroll
    for (int i = 0; i < 35; i++) A[i] = 0.f;
    int t = threadIdx.x;
    int T = gridDim.x * blockDim.x;
    for (int e = blockIdx.x * blockDim.x + t; e < NK; e += T){
        int id = nidx[e];
        int p = e >> 4, b = e >> 20;
        float4 cc = g_xyzT[p];
        float4 nb = g_xyzT[(b << 16) + id];
        float rx = cc.x - nb.x, ry = cc.y - nb.y, rz = cc.z - nb.z;
        float dis = sqrtf(rx*rx + ry*ry + rz*rz);
        A[0] += dis;       A[1] += dis*dis;
        A[2] += dis*cc.x;  A[3] += dis*cc.y;  A[4] += dis*cc.z;
        A[5] += dis*nb.x;  A[6] += dis*nb.y;  A[7] += dis*nb.z;
        A[8] += cc.x;  A[9] += cc.y;  A[10] += cc.z;
        A[11] += nb.x; A[12] += nb.y; A[13] += nb.z;
        A[14] += cc.x*cc.x; A[15] += cc.x*cc.y; A[16] += cc.x*cc.z;
        A[17] += cc.y*cc.y; A[18] += cc.y*cc.z; A[19] += cc.z*cc.z;
        A[20] += nb.x*nb.x; A[21] += nb.x*nb.y; A[22] += nb.x*nb.z;
        A[23] += nb.y*nb.y; A[24] += nb.y*nb.z; A[25] += nb.z*nb.z;
        A[26] += nb.x*cc.x; A[27] += nb.x*cc.y; A[28] += nb.x*cc.z;
        A[29] += nb.y*cc.x; A[30] += nb.y*cc.y; A[31] += nb.y*cc.z;
        A[32] += nb.z*cc.x; A[33] += nb.z*cc.y; A[34] += nb.z*cc.z;
    }
    __shared__ float red[35];
    if (t < 35) red[t] = 0.f;
    __syncthreads();
    int lane = t & 31;
    #pragma unroll
    for (int i = 0; i < 35; i++){
        float v = wsum(A[i]);
        if (lane == 0) atomicAdd(&red[i], v);
    }
    __syncthreads();
    if (t < 35) atomicAdd(&g_acc[t], red[t]);
}

__device__ __forceinline__ int s6(int i, int j){
    if (i > j){ int x = i; i = j; j = x; }
    return i * 3 - ((i * (i + 1)) >> 1) + j;
}

// ---------------- finalize BN1 from moments ----------------
__global__ void k_fin1(const float* __restrict__ w1, const float* __restrict__ b1,
                       const float* __restrict__ g, const float* __restrict__ be){
    __shared__ float S10[10], M10[100];
    int t = threadIdx.x;
    if (t == 0){
        float A[35];
        for (int i = 0; i < 35; i++) A[i] = g_acc[i];
        const float* Adc = A + 2; const float* Adn = A + 5;
        const float* Ac  = A + 8; const float* An  = A + 11;
        const float* Acc = A + 14; const float* Ann = A + 20; const float* Anc = A + 26;
        S10[0] = A[0];
        for (int i = 0; i < 3; i++){
            S10[1+i] = Ac[i] - An[i]; S10[4+i] = Ac[i]; S10[7+i] = An[i];
        }
        float M[10][10];
        M[0][0] = A[1];
        for (int i = 0; i < 3; i++){
            M[0][1+i] = Adc[i] - Adn[i];
            M[0][4+i] = Adc[i];
            M[0][7+i] = Adn[i];
        }
        for (int i = 0; i < 3; i++) for (int j = 0; j < 3; j++){
            float cc = Acc[s6(i,j)], nn = Ann[s6(i,j)];
            float nicj = Anc[i*3+j];
            float njci = Anc[j*3+i];
            M[1+i][1+j] = cc - nicj - njci + nn;
            M[1+i][4+j] = cc - nicj;
            M[1+i][7+j] = njci - nn;
            M[4+i][4+j] = cc;
            M[4+i][7+j] = njci;
            M[7+i][7+j] = nn;
        }
        for (int i = 0; i < 10; i++) for (int j = 0; j < i; j++) M[i][j] = M[j][i];
        for (int i = 0; i < 10; i++) for (int j = 0; j < 10; j++) M10[i*10+j] = M[i][j];
    }
    __syncthreads();
    if (t < 16){
        float w[10];
        #pragma unroll
        for (int j = 0; j < 10; j++) w[j] = w1[t*10+j];
        float b = b1[t];
        float sw = 0.f;
        #pragma unroll
        for (int j = 0; j < 10; j++) sw += w[j] * S10[j];
        float q = 0.f;
        for (int i = 0; i < 10; i++){
            float wi = w[i];
            for (int j = 0; j < 10; j++) q += wi * w[j] * M10[i*10+j];
        }
        const float inv = 1.f / (float)NK;
        float mean = sw * inv + b;
        float ey2 = (q + 2.f * b * sw) * inv + b * b;
        float var = ey2 - mean * mean;
        float sc = g[t] * rsqrtf(var + EPSV);
        g_bnp[t] = sc;
        g_bnp[16 + t] = be[t] - mean * sc;
    }
}

// ---------------- stage 1: pool1 + y2 stats (no store) + z1 stats ----------------
__global__ void __launch_bounds__(256, 3) k_stage1(
        const int* __restrict__ nidx, const float* __restrict__ w1, const float* __restrict__ b1,
        const float* __restrict__ w2, const float* __restrict__ b2,
        const float* __restrict__ wfc, const float* __restrict__ bfc,
        const float* __restrict__ wap, const float* __restrict__ bap){
    __shared__ float W1s[160], b1s[16], sc1[16], sh1[16], b2s[16], baps[16];
    __shared__ __align__(16) float W2s[256];
    __shared__ __align__(16) float WapT[32*16];
    __shared__ __align__(16) float fS[8][16][32];
    __shared__ __align__(16) float aggS[8][32];
    __shared__ float red[64];
    int t = threadIdx.x;
    if (t < 160) W1s[t] = w1[t];
    if (t < 256) W2s[t] = w2[t];
    if (t < 16){ b1s[t]=b1[t]; b2s[t]=b2[t]; sc1[t]=g_bnp[t]; sh1[t]=g_bnp[16+t]; baps[t]=bap[t]; }
    for (int i = t; i < 512; i += 256){ int o = i >> 5, c = i & 31; WapT[c * 16 + o] = wap[i]; }
    __syncthreads();
    int lane = t & 31, w = t >> 5, c2 = lane - 16;
    u64 wr2[16];
    #pragma unroll
    for (int j = 0; j < 16; j++) wr2[j] = pack2(wfc[lane * 32 + 2*j], wfc[lane * 32 + 2*j + 1]);
    float bfcl = bfc[lane];
    float sA = 0.f, ssA = 0.f;
    int warpsTotal = (gridDim.x * blockDim.x) >> 5;
    for (int pid = blockIdx.x * 8 + w; pid < NP; pid += warpsTotal){
        int b = pid >> 16;
        int idxl = nidx[(pid << 4) + (lane & 15)];
        float f[16];
        if (lane < 16){
            #pragma unroll
            for (int k = 0; k < 16; k++){
                int id = __shfl_sync(0x0000ffffu, idxl, k);
                f[k] = g_featT[((b << 16) + id) * CH + lane];
            }
        } else {
            float4 cc = g_xyzT[pid];
            const float* wp = W1s + c2 * 10;
            float w0=wp[0],w1r=wp[1],w2r=wp[2],w3=wp[3],w4=wp[4],
                  w5=wp[5],w6=wp[6],w7=wp[7],w8=wp[8],w9=wp[9];
            float base = b1s[c2] + w4*cc.x + w5*cc.y + w6*cc.z;
            float s1 = sc1[c2], h1 = sh1[c2];
            #pragma unroll
            for (int k = 0; k < 16; k++){
                int id = __shfl_sync(0xffff0000u, idxl, 16 + k);
                float4 nb = g_xyzT[(b << 16) + id];
                float rx = cc.x - nb.x, ry = cc.y - nb.y, rz = cc.z - nb.z;
                float dis = sqrtf(rx*rx + ry*ry + rz*rz);
                float y = base + w0*dis + w1r*rx + w2r*ry + w3*rz
                        + w7*nb.x + w8*nb.y + w9*nb.z;
                f[k] = lrelu(y * s1 + h1);
            }
        }
        #pragma unroll
        for (int k = 0; k < 16; k++) fS[w][k][lane] = f[k];
        __syncwarp();
        float att[16];
        #pragma unroll
        for (int k = 0; k < 16; k++){
            const ulonglong2* fp = reinterpret_cast<const ulonglong2*>(&fS[w][k][0]);
            u64 acc = 0ULL;
            #pragma unroll
            for (int i = 0; i < 8; i++){
                ulonglong2 u = fp[i];
                fma2(acc, u.x, wr2[2*i]);
                fma2(acc, u.y, wr2[2*i + 1]);
            }
            att[k] = lohi_sum(acc) + bfcl;
        }
        float m = att[0];
        #pragma unroll
        for (int k = 1; k < 16; k++) m = fmaxf(m, att[k]);
        float s = 0.f, agg = 0.f;
        #pragma unroll
        for (int k = 0; k < 16; k++){ float e = __expf(att[k] - m); s += e; agg += f[k] * e; }
        agg /= s;
        aggS[w][lane] = agg;
        __syncwarp();
        if (lane < 16){
            float z = baps[lane];
            #pragma unroll
            for (int c = 0; c < 32; c++) z += WapT[c * 16 + lane] * aggS[w][c];
            g_z1[pid * CH + lane] = z;
            sA += z; ssA += z * z;
        } else {
            const ulonglong2* w2p = reinterpret_cast<const ulonglong2*>(&W2s[c2 * 16]);
            ulonglong2 wv0 = w2p[0], wv1 = w2p[1], wv2 = w2p[2], wv3 = w2p[3];
            #pragma unroll
            for (int k = 0; k < 16; k++){
                const ulonglong2* xp = reinterpret_cast<const ulonglong2*>(&fS[w][k][16]);
                u64 acc = 0ULL;
                ulonglong2 u0 = xp[0], u1 = xp[1], u2 = xp[2], u3 = xp[3];
                fma2(acc, u0.x, wv0.x); fma2(acc, u0.y, wv0.y);
                fma2(acc, u1.x, wv1.x); fma2(acc, u1.y, wv1.y);
                fma2(acc, u2.x, wv2.x); fma2(acc, u2.y, wv2.y);
                fma2(acc, u3.x, wv3.x); fma2(acc, u3.y, wv3.y);
                float y2 = lohi_sum(acc) + b2s[c2];
                sA += y2; ssA += y2 * y2;
            }
        }
        __syncwarp();
    }
    if (t < 64) red[t] = 0.f;
    __syncthreads();
    atomicAdd(&red[lane], sA);
    atomicAdd(&red[32 + lane], ssA);
    __syncthreads();
    if (t < 32){
        int off = (t < 16) ? (96 + t) : (48 + t);   // z1 stats @96/112, y2 stats @64/80
        atomicAdd(&g_acc[off], red[t]);
        atomicAdd(&g_acc[off + 16], red[32 + t]);
    }
}

// ---------------- finalize BN2 (count NK) + BN ap1 (count NP) ----------------
__global__ void k_fin2AB(const float* __restrict__ g2, const float* __restrict__ be2,
                         const float* __restrict__ gA, const float* __restrict__ beA){
    int t = threadIdx.x;
    if (t < 16){
        float inv = 1.f / (float)NK;
        float m = g_acc[64 + t] * inv;
        float v = g_acc[80 + t] * inv - m * m;
        float sc = g2[t] * rsqrtf(v + EPSV);
        g_bnp[32 + t] = sc;
        g_bnp[48 + t] = be2[t] - m * sc;
    } else if (t < 32){
        int c = t - 16;
        float inv = 1.f / (float)NP;
        float m = g_acc[96 + c] * inv;
        float v = g_acc[112 + c] * inv - m * m;
        float sc = gA[c] * rsqrtf(v + EPSV);
        g_bnp[64 + c] = sc;
        g_bnp[80 + c] = beA[c] - m * sc;
    }
}

// ---------------- stage 2: recompute fx1/y2, pool2, fused z2 stats ----------------
__global__ void __launch_bounds__(256, 3) k_stage2(
        const int* __restrict__ nidx, const float* __restrict__ w1, const float* __restrict__ b1,
        const float* __restrict__ w2, const float* __restrict__ b2,
        const float* __restrict__ wfc, const float* __restrict__ bfc,
        const float* __restrict__ wap, const float* __restrict__ bap){
    __shared__ float W1s[160], b1s[16], sc1[16], sh1[16], sc2[16], sh2[16],
                     scA[16], shA[16], b2s[16], baps[32];
    __shared__ __align__(16) float W2s[256];
    __shared__ __align__(16) float WapT[32*32];
    __shared__ __align__(16) float fS[8][16][32];
    __shared__ __align__(16) float fx1S[8][16][16];
    __shared__ __align__(16) float aggS[8][32];
    __shared__ float red[64];
    int t = threadIdx.x;
    if (t < 160) W1s[t] = w1[t];
    if (t < 256) W2s[t] = w2[t];
    if (t < 16){
        b1s[t]=b1[t]; b2s[t]=b2[t];
        sc1[t]=g_bnp[t];    sh1[t]=g_bnp[16+t];
        sc2[t]=g_bnp[32+t]; sh2[t]=g_bnp[48+t];
        scA[t]=g_bnp[64+t]; shA[t]=g_bnp[80+t];
    }
    if (t < 32) baps[t] = bap[t];
    for (int i = t; i < 1024; i += 256){ int o = i >> 5, c = i & 31; WapT[c * 32 + o] = wap[i]; }
    __syncthreads();
    int lane = t & 31, w = t >> 5, c2 = lane - 16;
    u64 wr2[16];
    #pragma unroll
    for (int j = 0; j < 16; j++) wr2[j] = pack2(wfc[lane * 32 + 2*j], wfc[lane * 32 + 2*j + 1]);
    float bfcl = bfc[lane];
    float sA = 0.f, ssA = 0.f;
    int warpsTotal = (gridDim.x * blockDim.x) >> 5;
    for (int pid = blockIdx.x * 8 + w; pid < NP; pid += warpsTotal){
        int b = pid >> 16;
        int idxl = nidx[(pid << 4) + (lane & 15)];
        float f[16];
        if (lane < 16){
            float sa = scA[lane], ha = shA[lane];
            #pragma unroll
            for (int k = 0; k < 16; k++){
                int id = __shfl_sync(0x0000ffffu, idxl, k);
                float z = g_z1[((b << 16) + id) * CH + lane];
                f[k] = lrelu(z * sa + ha);
            }
        } else {
            float4 cc = g_xyzT[pid];
            const float* wp = W1s + c2 * 10;
            float w0=wp[0],w1r=wp[1],w2r=wp[2],w3=wp[3],w4=wp[4],
                  w5=wp[5],w6=wp[6],w7=wp[7],w8=wp[8],w9=wp[9];
            float base = b1s[c2] + w4*cc.x + w5*cc.y + w6*cc.z;
            float s1 = sc1[c2], h1 = sh1[c2];
            #pragma unroll
            for (int k = 0; k < 16; k++){
                int id = __shfl_sync(0xffff0000u, idxl, 16 + k);
                float4 nb = g_xyzT[(b << 16) + id];
                float rx = cc.x - nb.x, ry = cc.y - nb.y, rz = cc.z - nb.z;
                float dis = sqrtf(rx*rx + ry*ry + rz*rz);
                float y = base + w0*dis + w1r*rx + w2r*ry + w3*rz
                        + w7*nb.x + w8*nb.y + w9*nb.z;
                fx1S[w][k][c2] = lrelu(y * s1 + h1);
            }
            __syncwarp(0xffff0000u);
            const ulonglong2* w2p = reinterpret_cast<const ulonglong2*>(&W2s[c2 * 16]);
            ulonglong2 wv0 = w2p[0], wv1 = w2p[1], wv2 = w2p[2], wv3 = w2p[3];
            float s2 = sc2[c2], h2 = sh2[c2];
            #pragma unroll
            for (int k = 0; k < 16; k++){
                const ulonglong2* xp = reinterpret_cast<const ulonglong2*>(&fx1S[w][k][0]);
                u64 acc = 0ULL;
                ulonglong2 u0 = xp[0], u1 = xp[1], u2 = xp[2], u3 = xp[3];
                fma2(acc, u0.x, wv0.x); fma2(acc, u0.y, wv0.y);
                fma2(acc, u1.x, wv1.x); fma2(acc, u1.y, wv1.y);
                fma2(acc, u2.x, wv2.x); fma2(acc, u2.y, wv2.y);
                fma2(acc, u3.x, wv3.x); fma2(acc, u3.y, wv3.y);
                float y2 = lohi_sum(acc) + b2s[c2];
                f[k] = lrelu(y2 * s2 + h2);
            }
        }
        #pragma unroll
        for (int k = 0; k < 16; k++) fS[w][k][lane] = f[k];
        __syncwarp();
        float att[16];
        #pragma unroll
        for (int k = 0; k < 16; k++){
            const ulonglong2* fp = reinterpret_cast<const ulonglong2*>(&fS[w][k][0]);
            u64 acc = 0ULL;
            #pragma unroll
            for (int i = 0; i < 8; i++){
                ulonglong2 u = fp[i];
                fma2(acc, u.x, wr2[2*i]);
                fma2(acc, u.y, wr2[2*i + 1]);
            }
            att[k] = lohi_sum(acc) + bfcl;
        }
        float m = att[0];
        #pragma unroll
        for (int k = 1; k < 16; k++) m = fmaxf(m, att[k]);
        float s = 0.f, agg = 0.f;
        #pragma unroll
        for (int k = 0; k < 16; k++){ float e = __expf(att[k] - m); s += e; agg += f[k] * e; }
        agg /= s;
        aggS[w][lane] = agg;
        __syncwarp();
        float z = baps[lane];
        #pragma unroll
        for (int c = 0; c < 32; c++) z += WapT[c * 32 + lane] * aggS[w][c];
        g_z2[pid * CO + lane] = z;
        sA += z; ssA += z * z;
        __syncwarp();
    }
    if (t < 64) red[t] = 0.f;
    __syncthreads();
    atomicAdd(&red[lane], sA);
    atomicAdd(&red[32 + lane], ssA);
    __syncthreads();
    if (t < 32){
        atomicAdd(&g_acc[128 + t], red[t]);
        atomicAdd(&g_acc[160 + t], red[32 + t]);
    }
}

// ---------------- finalize BN ap2 ----------------
__global__ void k_finB(const float* __restrict__ g, const float* __restrict__ be){
    int t = threadIdx.x;
    if (t < 32){
        float inv = 1.f / (float)NP;
        float m = g_acc[128 + t] * inv;
        float v = g_acc[160 + t] * inv - m * m;
        float sc = g[t] * rsqrtf(v + EPSV);
        g_bnp[96 + t] = sc;
        g_bnp[128 + t] = be[t] - m * sc;
    }
}

// ---------------- final BN+LReLU + transpose to output layout ----------------
__global__ void k_out(float* __restrict__ out){
    __shared__ float tile[32][33];
    int bx = blockIdx.x;
    int b = bx >> 11;
    int n0 = (bx & 2047) << 5;
    int tx = threadIdx.x, ty = threadIdx.y;
    #pragma unroll
    for (int i = 0; i < 4; i++){
        int r = ty + i * 8;
        tile[r][tx] = g_z2[((b << 16) + n0 + r) * CO + tx];
    }
    __syncthreads();
    #pragma unroll
    for (int i = 0; i < 4; i++){
        int c = ty + i * 8;
        float v = tile[tx][c] * g_bnp[96 + c] + g_bnp[128 + c];
        out[(b * CO + c) * NPTS + n0 + tx] = lrelu(v);
    }
}

extern "C" void kernel_launch(void* const* d_in, const int* in_sizes, int n_in,
                              void* d_out, int out_size){
    const float* xyz     = (const float*)d_in[0];
    const float* feature = (const float*)d_in[1];
    const int*   nidx    = (const int*)  d_in[2];
    const float* w_mlp1  = (const float*)d_in[3];
    const float* b_mlp1  = (const float*)d_in[4];
    const float* g_mlp1  = (const float*)d_in[5];
    const float* be_mlp1 = (const float*)d_in[6];
    const float* w_fc1   = (const float*)d_in[7];
    const float* b_fc1   = (const float*)d_in[8];
    const float* w_ap1   = (const float*)d_in[9];
    const float* b_ap1   = (const float*)d_in[10];
    const float* g_ap1   = (const float*)d_in[11];
    const float* be_ap1  = (const float*)d_in[12];
    const float* w_mlp2  = (const float*)d_in[13];
    const float* b_mlp2  = (const float*)d_in[14];
    const float* g_mlp2  = (const float*)d_in[15];
    const float* be_mlp2 = (const float*)d_in[16];
    const float* w_fc2   = (const float*)d_in[17];
    const float* b_fc2   = (const float*)d_in[18];
    const float* w_ap2   = (const float*)d_in[19];
    const float* b_ap2   = (const float*)d_in[20];
    const float* g_ap2   = (const float*)d_in[21];
    const float* be_ap2  = (const float*)d_in[22];
    float* out = (float*)d_out;

    k_t01<<<512, 256>>>(xyz, feature);
    k_stats1e<<<512, 256>>>(nidx);
    k_fin1<<<1, 32>>>(w_mlp1, b_mlp1, g_mlp1, be_mlp1);
    k_stage1<<<1024, 256>>>(nidx, w_mlp1, b_mlp1, w_mlp2, b_mlp2, w_fc1, b_fc1, w_ap1, b_ap1);
    k_fin2AB<<<1, 32>>>(g_mlp2, be_mlp2, g_ap1, be_ap1);
    k_stage2<<<1024, 256>>>(nidx, w_mlp1, b_mlp1, w_mlp2, b_mlp2, w_fc2, b_fc2, w_ap2, b_ap2);
    k_finB<<<1, 32>>>(g_ap2, be_ap2);
    dim3 bt(32, 8);
    k_out<<<4096, bt>>>(out);
}

// round 12
// speedup vs baseline: 2.2335x; 1.1534x over previous
#include <cuda_runtime.h>

#define BS 2
#define NPTS 65536
#define KNN 16
#define CH 16
#define CO 32
#define NK (BS*NPTS*KNN)
#define NP (BS*NPTS)
#define EPSV 1e-5f
#define SLOPE 0.2f

// ---------------- scratch ----------------
__device__ float4 g_xyzT[NP];            // [b*N+n] = {x,y,z,0}
__device__ float  g_featT[NP*CH];        // [b*N+n][16]
__device__ float  g_z1[NP*CH];           // stage1 pre-BN pooled output
__device__ float  g_z2[NP*CO];           // stage2 pre-BN pooled output
__device__ float  g_acc[192];            // stat sums
__device__ float  g_bnp[192];            // finalized BN scale/shift

typedef unsigned long long u64;

__device__ __forceinline__ u64 pack2(float lo, float hi){
    u64 r; asm("mov.b64 %0, {%1,%2};" : "=l"(r) : "f"(lo), "f"(hi)); return r;
}
__device__ __forceinline__ void fma2(u64 &d, u64 a, u64 b){
    asm("fma.rn.f32x2 %0, %1, %2, %3;" : "=l"(d) : "l"(a), "l"(b), "l"(d));
}
__device__ __forceinline__ float lohi_sum(u64 v){
    float lo, hi; asm("mov.b64 {%0,%1}, %2;" : "=f"(lo), "=f"(hi) : "l"(v)); return lo + hi;
}
__device__ __forceinline__ float lrelu(float x){ return x >= 0.f ? x : SLOPE * x; }
__device__ __forceinline__ float wsum(float v){
    #pragma unroll
    for (int o = 16; o; o >>= 1) v += __shfl_down_sync(0xffffffffu, v, o);
    return v;
}

// ---------------- transpose xyz + feature, zero accumulators ----------------
__global__ void k_t01(const float* __restrict__ xyz, const float* __restrict__ feat){
    int i = blockIdx.x * blockDim.x + threadIdx.x;   // grid exactly covers NP
    if (blockIdx.x == 0 && threadIdx.x < 192) g_acc[threadIdx.x] = 0.f;
    int b = i >> 16, n = i & 65535;
    const float* xp = xyz + b * 3 * NPTS;
    g_xyzT[i] = make_float4(xp[n], xp[NPTS + n], xp[2 * NPTS + n], 0.f);
    const float* fp = feat + b * CH * NPTS + n;
    float4* dst = reinterpret_cast<float4*>(&g_featT[i * CH]);
    #pragma unroll
    for (int q = 0; q < 4; q++){
        float4 v;
        v.x = fp[(4*q + 0) * NPTS];
        v.y = fp[(4*q + 1) * NPTS];
        v.z = fp[(4*q + 2) * NPTS];
        v.w = fp[(4*q + 3) * NPTS];
        dst[q] = v;
    }
}

// ---------------- per-edge raw moments for exact BN1 stats ----------------
__global__ void __launch_bounds__(256) k_stats1e(const int* __restrict__ nidx){
    float A[35];
    #pragma unroll
    for (int i = 0; i < 35; i++) A[i] = 0.f;
    int t = threadIdx.x;
    int T = gridDim.x * blockDim.x;
    for (int e = blockIdx.x * blockDim.x + t; e < NK; e += T){
        int id = nidx[e];
        int p = e >> 4, b = e >> 20;
        float4 cc = g_xyzT[p];
        float4 nb = g_xyzT[(b << 16) + id];
        float rx = cc.x - nb.x, ry = cc.y - nb.y, rz = cc.z - nb.z;
        float dis = sqrtf(rx*rx + ry*ry + rz*rz);
        A[0] += dis;       A[1] += dis*dis;
        A[2] += dis*cc.x;  A[3] += dis*cc.y;  A[4] += dis*cc.z;
        A[5] += dis*nb.x;  A[6] += dis*nb.y;  A[7] += dis*nb.z;
        A[8] += cc.x;  A[9] += cc.y;  A[10] += cc.z;
        A[11] += nb.x; A[12] += nb.y; A[13] += nb.z;
        A[14] += cc.x*cc.x; A[15] += cc.x*cc.y; A[16] += cc.x*cc.z;
        A[17] += cc.y*cc.y; A[18] += cc.y*cc.z; A[19] += cc.z*cc.z;
        A[20] += nb.x*nb.x; A[21] += nb.x*nb.y; A[22] += nb.x*nb.z;
        A[23] += nb.y*nb.y; A[24] += nb.y*nb.z; A[25] += nb.z*nb.z;
        A[26] += nb.x*cc.x; A[27] += nb.x*cc.y; A[28] += nb.x*cc.z;
        A[29] += nb.y*cc.x; A[30] += nb.y*cc.y; A[31] += nb.y*cc.z;
        A[32] += nb.z*cc.x; A[33] += nb.z*cc.y; A[34] += nb.z*cc.z;
    }
    __shared__ float red[35];
    if (t < 35) red[t] = 0.f;
    __syncthreads();
    int lane = t & 31;
    #pragma unroll
    for (int i = 0; i < 35; i++){
        float v = wsum(A[i]);
        if (lane == 0) atomicAdd(&red[i], v);
    }
    __syncthreads();
    if (t < 35) atomicAdd(&g_acc[t], red[t]);
}

__device__ __forceinline__ int s6(int i, int j){
    if (i > j){ int x = i; i = j; j = x; }
    return i * 3 - ((i * (i + 1)) >> 1) + j;
}

// ---------------- finalize BN1 from moments ----------------
__global__ void k_fin1(const float* __restrict__ w1, const float* __restrict__ b1,
                       const float* __restrict__ g, const float* __restrict__ be){
    __shared__ float S10[10], M10[100];
    int t = threadIdx.x;
    if (t == 0){
        float A[35];
        for (int i = 0; i < 35; i++) A[i] = g_acc[i];
        const float* Adc = A + 2; const float* Adn = A + 5;
        const float* Ac  = A + 8; const float* An  = A + 11;
        const float* Acc = A + 14; const float* Ann = A + 20; const float* Anc = A + 26;
        S10[0] = A[0];
        for (int i = 0; i < 3; i++){
            S10[1+i] = Ac[i] - An[i]; S10[4+i] = Ac[i]; S10[7+i] = An[i];
        }
        float M[10][10];
        M[0][0] = A[1];
        for (int i = 0; i < 3; i++){
            M[0][1+i] = Adc[i] - Adn[i];
            M[0][4+i] = Adc[i];
            M[0][7+i] = Adn[i];
        }
        for (int i = 0; i < 3; i++) for (int j = 0; j < 3; j++){
            float cc = Acc[s6(i,j)], nn = Ann[s6(i,j)];
            float nicj = Anc[i*3+j];
            float njci = Anc[j*3+i];
            M[1+i][1+j] = cc - nicj - njci + nn;
            M[1+i][4+j] = cc - nicj;
            M[1+i][7+j] = njci - nn;
            M[4+i][4+j] = cc;
            M[4+i][7+j] = njci;
            M[7+i][7+j] = nn;
        }
        for (int i = 0; i < 10; i++) for (int j = 0; j < i; j++) M[i][j] = M[j][i];
        for (int i = 0; i < 10; i++) for (int j = 0; j < 10; j++) M10[i*10+j] = M[i][j];
    }
    __syncthreads();
    if (t < 16){
        float w[10];
        #pragma unroll
        for (int j = 0; j < 10; j++) w[j] = w1[t*10+j];
        float b = b1[t];
        float sw = 0.f;
        #pragma unroll
        for (int j = 0; j < 10; j++) sw += w[j] * S10[j];
        float q = 0.f;
        for (int i = 0; i < 10; i++){
            float wi = w[i];
            for (int j = 0; j < 10; j++) q += wi * w[j] * M10[i*10+j];
        }
        const float inv = 1.f / (float)NK;
        float mean = sw * inv + b;
        float ey2 = (q + 2.f * b * sw) * inv + b * b;
        float var = ey2 - mean * mean;
        float sc = g[t] * rsqrtf(var + EPSV);
        g_bnp[t] = sc;
        g_bnp[16 + t] = be[t] - mean * sc;
    }
}

// ---------------- stage 1: pool1 + all-lane y2 stats + z1 stats ----------------
__global__ void __launch_bounds__(256, 4) k_stage1(
        const int* __restrict__ nidx, const float* __restrict__ w1, const float* __restrict__ b1,
        const float* __restrict__ w2, const float* __restrict__ b2,
        const float* __restrict__ wfc, const float* __restrict__ bfc,
        const float* __restrict__ wap, const float* __restrict__ bap){
    __shared__ float W1s[160], b1s[16], sc1[16], sh1[16], b2s[16], baps[16];
    __shared__ __align__(16) float W2s[256];
    __shared__ __align__(16) float WapT[32*16];
    __shared__ __align__(16) float fS[8][16][32];
    __shared__ __align__(16) float aggS[8][32];
    __shared__ float red[64];
    int t = threadIdx.x;
    if (t < 160) W1s[t] = w1[t];
    if (t < 256) W2s[t] = w2[t];
    if (t < 16){ b1s[t]=b1[t]; b2s[t]=b2[t]; sc1[t]=g_bnp[t]; sh1[t]=g_bnp[16+t]; baps[t]=bap[t]; }
    for (int i = t; i < 512; i += 256){ int o = i >> 5, c = i & 31; WapT[c * 16 + o] = wap[i]; }
    __syncthreads();
    int lane = t & 31, w = t >> 5, c2 = lane - 16;
    int cL = lane & 15, h = lane >> 4;
    u64 wr2[16];
    #pragma unroll
    for (int j = 0; j < 16; j++) wr2[j] = pack2(wfc[lane * 32 + 2*j], wfc[lane * 32 + 2*j + 1]);
    float bfcl = bfc[lane];
    u64 w2r[8];
    {
        const ulonglong2* wpp = reinterpret_cast<const ulonglong2*>(&W2s[cL * 16]);
        ulonglong2 q0 = wpp[0], q1 = wpp[1], q2 = wpp[2], q3 = wpp[3];
        w2r[0]=q0.x; w2r[1]=q0.y; w2r[2]=q1.x; w2r[3]=q1.y;
        w2r[4]=q2.x; w2r[5]=q2.y; w2r[6]=q3.x; w2r[7]=q3.y;
    }
    float b2l = b2s[cL];
    float sZ = 0.f, ssZ = 0.f, sY = 0.f, ssY = 0.f;
    int warpsTotal = (gridDim.x * blockDim.x) >> 5;
    for (int pid = blockIdx.x * 8 + w; pid < NP; pid += warpsTotal){
        int b = pid >> 16;
        int idxl = nidx[(pid << 4) + cL];
        if (lane < 16){
            #pragma unroll
            for (int k = 0; k < 16; k++){
                int id = __shfl_sync(0x0000ffffu, idxl, k);
                fS[w][k][lane] = g_featT[((b << 16) + id) * CH + lane];
            }
        } else {
            float4 cc = g_xyzT[pid];
            const float* wp = W1s + c2 * 10;
            float w0=wp[0],w1r=wp[1],w2r_=wp[2],w3=wp[3],w4=wp[4],
                  w5=wp[5],w6=wp[6],w7=wp[7],w8=wp[8],w9=wp[9];
            float base = b1s[c2] + w4*cc.x + w5*cc.y + w6*cc.z;
            float s1 = sc1[c2], h1 = sh1[c2];
            #pragma unroll
            for (int k = 0; k < 16; k++){
                int id = __shfl_sync(0xffff0000u, idxl, 16 + k);
                float4 nb = g_xyzT[(b << 16) + id];
                float rx = cc.x - nb.x, ry = cc.y - nb.y, rz = cc.z - nb.z;
                float dis = sqrtf(rx*rx + ry*ry + rz*rz);
                float y = base + w0*dis + w1r*rx + w2r_*ry + w3*rz
                        + w7*nb.x + w8*nb.y + w9*nb.z;
                fS[w][k][lane] = lrelu(y * s1 + h1);
            }
        }
        __syncwarp();
        float att[16];
        #pragma unroll
        for (int k = 0; k < 16; k++){
            const ulonglong2* fp = reinterpret_cast<const ulonglong2*>(&fS[w][k][0]);
            u64 acc0 = 0ULL, acc1 = 0ULL;
            #pragma unroll
            for (int i = 0; i < 4; i++){
                ulonglong2 ua = fp[i];
                ulonglong2 ub = fp[i + 4];
                fma2(acc0, ua.x, wr2[2*i]);     fma2(acc0, ua.y, wr2[2*i + 1]);
                fma2(acc1, ub.x, wr2[2*i + 8]); fma2(acc1, ub.y, wr2[2*i + 9]);
            }
            att[k] = lohi_sum(acc0) + lohi_sum(acc1) + bfcl;
        }
        float m = att[0];
        #pragma unroll
        for (int k = 1; k < 16; k++) m = fmaxf(m, att[k]);
        float s = 0.f, agg = 0.f;
        #pragma unroll
        for (int k = 0; k < 16; k++){
            float e = __expf(att[k] - m);
            s += e;
            agg += fS[w][k][lane] * e;
        }
        agg /= s;
        aggS[w][lane] = agg;
        __syncwarp();
        if (lane < 16){
            float zA = baps[lane], zB = 0.f;
            #pragma unroll
            for (int c = 0; c < 32; c += 2){
                zA += WapT[c * 16 + lane] * aggS[w][c];
                zB += WapT[(c + 1) * 16 + lane] * aggS[w][c + 1];
            }
            float z = zA + zB;
            g_z1[pid * CH + lane] = z;
            sZ += z; ssZ += z * z;
        }
        // all-lane y2 stats: lane handles outputs (k = 2*i + h, c = cL)
        #pragma unroll
        for (int i = 0; i < 8; i++){
            int k = 2 * i + h;
            const ulonglong2* xp = reinterpret_cast<const ulonglong2*>(&fS[w][k][16]);
            u64 acc0 = 0ULL, acc1 = 0ULL;
            ulonglong2 u0 = xp[0], u1 = xp[1], u2 = xp[2], u3 = xp[3];
            fma2(acc0, u0.x, w2r[0]); fma2(acc0, u0.y, w2r[1]);
            fma2(acc0, u1.x, w2r[2]); fma2(acc0, u1.y, w2r[3]);
            fma2(acc1, u2.x, w2r[4]); fma2(acc1, u2.y, w2r[5]);
            fma2(acc1, u3.x, w2r[6]); fma2(acc1, u3.y, w2r[7]);
            float y2 = lohi_sum(acc0) + lohi_sum(acc1) + b2l;
            sY += y2; ssY += y2 * y2;
        }
        __syncwarp();
    }
    // epilogue: [0:16) z1 sum, [16:32) z1 sumsq, [32:48) y2 sum, [48:64) y2 sumsq
    if (t < 64) red[t] = 0.f;
    __syncthreads();
    if (lane < 16){
        atomicAdd(&red[lane], sZ);
        atomicAdd(&red[16 + lane], ssZ);
    }
    atomicAdd(&red[32 + cL], sY);
    atomicAdd(&red[48 + cL], ssY);
    __syncthreads();
    if (t < 16){
        atomicAdd(&g_acc[96 + t], red[t]);        // z1 stats (BN ap1)
        atomicAdd(&g_acc[112 + t], red[16 + t]);
        atomicAdd(&g_acc[64 + t], red[32 + t]);   // y2 stats (BN2)
        atomicAdd(&g_acc[80 + t], red[48 + t]);
    }
}

// ---------------- finalize BN2 (count NK) + BN ap1 (count NP) ----------------
__global__ void k_fin2AB(const float* __restrict__ g2, const float* __restrict__ be2,
                         const float* __restrict__ gA, const float* __restrict__ beA){
    int t = threadIdx.x;
    if (t < 16){
        float inv = 1.f / (float)NK;
        float m = g_acc[64 + t] * inv;
        float v = g_acc[80 + t] * inv - m * m;
        float sc = g2[t] * rsqrtf(v + EPSV);
        g_bnp[32 + t] = sc;
        g_bnp[48 + t] = be2[t] - m * sc;
    } else if (t < 32){
        int c = t - 16;
        float inv = 1.f / (float)NP;
        float m = g_acc[96 + c] * inv;
        float v = g_acc[112 + c] * inv - m * m;
        float sc = gA[c] * rsqrtf(v + EPSV);
        g_bnp[64 + c] = sc;
        g_bnp[80 + c] = beA[c] - m * sc;
    }
}

// ---------------- stage 2: recompute fx1, all-lane y2, pool2, fused z2 stats ----------------
__global__ void __launch_bounds__(256, 4) k_stage2(
        const int* __restrict__ nidx, const float* __restrict__ w1, const float* __restrict__ b1,
        const float* __restrict__ w2, const float* __restrict__ b2,
        const float* __restrict__ wfc, const float* __restrict__ bfc,
        const float* __restrict__ wap, const float* __restrict__ bap){
    __shared__ float W1s[160], b1s[16], sc1[16], sh1[16], sc2[16], sh2[16],
                     scA[16], shA[16], b2s[16], baps[32];
    __shared__ __align__(16) float W2s[256];
    __shared__ __align__(16) float WapT[32*32];
    __shared__ __align__(16) float fS[8][16][32];
    __shared__ __align__(16) float fx1S[8][16][16];
    __shared__ __align__(16) float aggS[8][32];
    __shared__ float red[64];
    int t = threadIdx.x;
    if (t < 160) W1s[t] = w1[t];
    if (t < 256) W2s[t] = w2[t];
    if (t < 16){
        b1s[t]=b1[t]; b2s[t]=b2[t];
        sc1[t]=g_bnp[t];    sh1[t]=g_bnp[16+t];
        sc2[t]=g_bnp[32+t]; sh2[t]=g_bnp[48+t];
        scA[t]=g_bnp[64+t]; shA[t]=g_bnp[80+t];
    }
    if (t < 32) baps[t] = bap[t];
    for (int i = t; i < 1024; i += 256){ int o = i >> 5, c = i & 31; WapT[c * 32 + o] = wap[i]; }
    __syncthreads();
    int lane = t & 31, w = t >> 5, c2 = lane - 16;
    int cL = lane & 15, h = lane >> 4;
    u64 wr2[16];
    #pragma unroll
    for (int j = 0; j < 16; j++) wr2[j] = pack2(wfc[lane * 32 + 2*j], wfc[lane * 32 + 2*j + 1]);
    float bfcl = bfc[lane];
    u64 w2r[8];
    {
        const ulonglong2* wpp = reinterpret_cast<const ulonglong2*>(&W2s[cL * 16]);
        ulonglong2 q0 = wpp[0], q1 = wpp[1], q2 = wpp[2], q3 = wpp[3];
        w2r[0]=q0.x; w2r[1]=q0.y; w2r[2]=q1.x; w2r[3]=q1.y;
        w2r[4]=q2.x; w2r[5]=q2.y; w2r[6]=q3.x; w2r[7]=q3.y;
    }
    float b2l = b2s[cL], s2l = sc2[cL], h2l = sh2[cL];
    float sA = 0.f, ssA = 0.f;
    int warpsTotal = (gridDim.x * blockDim.x) >> 5;
    for (int pid = blockIdx.x * 8 + w; pid < NP; pid += warpsTotal){
        int b = pid >> 16;
        int idxl = nidx[(pid << 4) + cL];
        if (lane < 16){
            float sa = scA[lane], ha = shA[lane];
            #pragma unroll
            for (int k = 0; k < 16; k++){
                int id = __shfl_sync(0x0000ffffu, idxl, k);
                float z = g_z1[((b << 16) + id) * CH + lane];
                fS[w][k][lane] = lrelu(z * sa + ha);
            }
        } else {
            float4 cc = g_xyzT[pid];
            const float* wp = W1s + c2 * 10;
            float w0=wp[0],w1r=wp[1],w2r_=wp[2],w3=wp[3],w4=wp[4],
                  w5=wp[5],w6=wp[6],w7=wp[7],w8=wp[8],w9=wp[9];
            float base = b1s[c2] + w4*cc.x + w5*cc.y + w6*cc.z;
            float s1 = sc1[c2], h1 = sh1[c2];
            #pragma unroll
            for (int k = 0; k < 16; k++){
                int id = __shfl_sync(0xffff0000u, idxl, 16 + k);
                float4 nb = g_xyzT[(b << 16) + id];
                float rx = cc.x - nb.x, ry = cc.y - nb.y, rz = cc.z - nb.z;
                float dis = sqrtf(rx*rx + ry*ry + rz*rz);
                float y = base + w0*dis + w1r*rx + w2r_*ry + w3*rz
                        + w7*nb.x + w8*nb.y + w9*nb.z;
                fx1S[w][k][c2] = lrelu(y * s1 + h1);
            }
        }
        __syncwarp();
        // all-lane y2: lane handles outputs (k = 2*i + h, c = cL); writes f into fS
        #pragma unroll
        for (int i = 0; i < 8; i++){
            int k = 2 * i + h;
            const ulonglong2* xp = reinterpret_cast<const ulonglong2*>(&fx1S[w][k][0]);
            u64 acc0 = 0ULL, acc1 = 0ULL;
            ulonglong2 u0 = xp[0], u1 = xp[1], u2 = xp[2], u3 = xp[3];
            fma2(acc0, u0.x, w2r[0]); fma2(acc0, u0.y, w2r[1]);
            fma2(acc0, u1.x, w2r[2]); fma2(acc0, u1.y, w2r[3]);
            fma2(acc1, u2.x, w2r[4]); fma2(acc1, u2.y, w2r[5]);
            fma2(acc1, u3.x, w2r[6]); fma2(acc1, u3.y, w2r[7]);
            float y2 = lohi_sum(acc0) + lohi_sum(acc1) + b2l;
            fS[w][k][16 + cL] = lrelu(y2 * s2l + h2l);
        }
        __syncwarp();
        float att[16];
        #pragma unroll
        for (int k = 0; k < 16; k++){
            const ulonglong2* fp = reinterpret_cast<const ulonglong2*>(&fS[w][k][0]);
            u64 acc0 = 0ULL, acc1 = 0ULL;
            #pragma unroll
            for (int i = 0; i < 4; i++){
                ulonglong2 ua = fp[i];
                ulonglong2 ub = fp[i + 4];
                fma2(acc0, ua.x, wr2[2*i]);     fma2(acc0, ua.y, wr2[2*i + 1]);
                fma2(acc1, ub.x, wr2[2*i + 8]); fma2(acc1, ub.y, wr2[2*i + 9]);
            }
            att[k] = lohi_sum(acc0) + lohi_sum(acc1) + bfcl;
        }
        float m = att[0];
        #pragma unroll
        for (int k = 1; k < 16; k++) m = fmaxf(m, att[k]);
        float s = 0.f, agg = 0.f;
        #pragma unroll
        for (int k = 0; k < 16; k++){
            float e = __expf(att[k] - m);
            s += e;
            agg += fS[w][k][lane] * e;
        }
        agg /= s;
        aggS[w][lane] = agg;
        __syncwarp();
        float zA = baps[lane], zB = 0.f;
        #pragma unroll
        for (int c = 0; c < 32; c += 2){
            zA += WapT[c * 32 + lane] * aggS[w][c];
            zB += WapT[(c + 1) * 32 + lane] * aggS[w][c + 1];
        }
        float z = zA + zB;
        g_z2[pid * CO + lane] = z;
        sA += z; ssA += z * z;
        __syncwarp();
    }
    if (t < 64) red[t] = 0.f;
    __syncthreads();
    atomicAdd(&red[lane], sA);
    atomicAdd(&red[32 + lane], ssA);
    __syncthreads();
    if (t < 32){
        atomicAdd(&g_acc[128 + t], red[t]);
        atomicAdd(&g_acc[160 + t], red[32 + t]);
    }
}

// ---------------- finalize BN ap2 ----------------
__global__ void k_finB(const float* __restrict__ g, const float* __restrict__ be){
    int t = threadIdx.x;
    if (t < 32){
        float inv = 1.f / (float)NP;
        float m = g_acc[128 + t] * inv;
        float v = g_acc[160 + t] * inv - m * m;
        float sc = g[t] * rsqrtf(v + EPSV);
        g_bnp[96 + t] = sc;
        g_bnp[128 + t] = be[t] - m * sc;
    }
}

// ---------------- final BN+LReLU + transpose to output layout ----------------
__global__ void k_out(float* __restrict__ out){
    __shared__ float tile[32][33];
    int bx = blockIdx.x;
    int b = bx >> 11;
    int n0 = (bx & 2047) << 5;
    int tx = threadIdx.x, ty = threadIdx.y;
    #pragma unroll
    for (int i = 0; i < 4; i++){
        int r = ty + i * 8;
        tile[r][tx] = g_z2[((b << 16) + n0 + r) * CO + tx];
    }
    __syncthreads();
    #pragma unroll
    for (int i = 0; i < 4; i++){
        int c = ty + i * 8;
        float v = tile[tx][c] * g_bnp[96 + c] + g_bnp[128 + c];
        out[(b * CO + c) * NPTS + n0 + tx] = lrelu(v);
    }
}

extern "C" void kernel_launch(void* const* d_in, const int* in_sizes, int n_in,
                              void* d_out, int out_size){
    const float* xyz     = (const float*)d_in[0];
    const float* feature = (const float*)d_in[1];
    const int*   nidx    = (const int*)  d_in[2];
    const float* w_mlp1  = (const float*)d_in[3];
    const float* b_mlp1  = (const float*)d_in[4];
    const float* g_mlp1  = (const float*)d_in[5];
    const float* be_mlp1 = (const float*)d_in[6];
    const float* w_fc1   = (const float*)d_in[7];
    const float* b_fc1   = (const float*)d_in[8];
    const float* w_ap1   = (const float*)d_in[9];
    const float* b_ap1   = (const float*)d_in[10];
    const float* g_ap1   = (const float*)d_in[11];
    const float* be_ap1  = (const float*)d_in[12];
    const float* w_mlp2  = (const float*)d_in[13];
    const float* b_mlp2  = (const float*)d_in[14];
    const float* g_mlp2  = (const float*)d_in[15];
    const float* be_mlp2 = (const float*)d_in[16];
    const float* w_fc2   = (const float*)d_in[17];
    const float* b_fc2   = (const float*)d_in[18];
    const float* w_ap2   = (const float*)d_in[19];
    const float* b_ap2   = (const float*)d_in[20];
    const float* g_ap2   = (const float*)d_in[21];
    const float* be_ap2  = (const float*)d_in[22];
    float* out = (float*)d_out;

    k_t01<<<512, 256>>>(xyz, feature);
    k_stats1e<<<512, 256>>>(nidx);
    k_fin1<<<1, 32>>>(w_mlp1, b_mlp1, g_mlp1, be_mlp1);
    k_stage1<<<1024, 256>>>(nidx, w_mlp1, b_mlp1, w_mlp2, b_mlp2, w_fc1, b_fc1, w_ap1, b_ap1);
    k_fin2AB<<<1, 32>>>(g_mlp2, be_mlp2, g_ap1, be_ap1);
    k_stage2<<<1024, 256>>>(nidx, w_mlp1, b_mlp1, w_mlp2, b_mlp2, w_fc2, b_fc2, w_ap2, b_ap2);
    k_finB<<<1, 32>>>(g_ap2, be_ap2);
    dim3 bt(32, 8);
    k_out<<<4096, bt>>>(out);
}

// round 15
// speedup vs baseline: 2.4495x; 1.0967x over previous
#include <cuda_runtime.h>

#define BS 2
#define NPTS 65536
#define KNN 16
#define CH 16
#define CO 32
#define NK (BS*NPTS*KNN)
#define NP (BS*NPTS)
#define EPSV 1e-5f
#define SLOPE 0.2f
#define SGRID 592   // 148 SMs x 4 blocks: single wave

// ---------------- scratch ----------------
__device__ float4 g_xyzT[NP];            // [b*N+n] = {x,y,z,0}
__device__ float  g_featT[NP*CH];        // [b*N+n][16]
__device__ float  g_z1[NP*CH];           // stage1 pre-BN pooled output
__device__ float  g_z2[NP*CO];           // stage2 pre-BN pooled output
__device__ float  g_acc[192];            // stat sums
__device__ float  g_bnp[192];            // finalized BN scale/shift

typedef unsigned long long u64;

__device__ __forceinline__ u64 pack2(float lo, float hi){
    u64 r; asm("mov.b64 %0, {%1,%2};" : "=l"(r) : "f"(lo), "f"(hi)); return r;
}
__device__ __forceinline__ void fma2(u64 &d, u64 a, u64 b){
    asm("fma.rn.f32x2 %0, %1, %2, %3;" : "=l"(d) : "l"(a), "l"(b), "l"(d));
}
__device__ __forceinline__ float lohi_sum(u64 v){
    float lo, hi; asm("mov.b64 {%0,%1}, %2;" : "=f"(lo), "=f"(hi) : "l"(v)); return lo + hi;
}
__device__ __forceinline__ float lrelu(float x){ return x >= 0.f ? x : SLOPE * x; }
__device__ __forceinline__ float wsum(float v){
    #pragma unroll
    for (int o = 16; o; o >>= 1) v += __shfl_down_sync(0xffffffffu, v, o);
    return v;
}

// ---------------- transpose xyz + feature, zero accumulators ----------------
__global__ void k_t01(const float* __restrict__ xyz, const float* __restrict__ feat){
    int i = blockIdx.x * blockDim.x + threadIdx.x;   // grid exactly covers NP
    if (blockIdx.x == 0 && threadIdx.x < 192) g_acc[threadIdx.x] = 0.f;
    int b = i >> 16, n = i & 65535;
    const float* xp = xyz + b * 3 * NPTS;
    g_xyzT[i] = make_float4(xp[n], xp[NPTS + n], xp[2 * NPTS + n], 0.f);
    const float* fp = feat + b * CH * NPTS + n;
    float4* dst = reinterpret_cast<float4*>(&g_featT[i * CH]);
    #pragma unroll
    for (int q = 0; q < 4; q++){
        float4 v;
        v.x = fp[(4*q + 0) * NPTS];
        v.y = fp[(4*q + 1) * NPTS];
        v.z = fp[(4*q + 2) * NPTS];
        v.w = fp[(4*q + 3) * NPTS];
        dst[q] = v;
    }
}

// ---------------- per-edge raw moments for exact BN1 stats ----------------
__global__ void __launch_bounds__(256) k_stats1e(const int* __restrict__ nidx){
    float A[35];
    #pragma unroll
    for (int i = 0; i < 35; i++) A[i] = 0.f;
    int t = threadIdx.x;
    int T = gridDim.x * blockDim.x;
    for (int e = blockIdx.x * blockDim.x + t; e < NK; e += T){
        int id = nidx[e];
        int p = e >> 4, b = e >> 20;
        float4 cc = g_xyzT[p];
        float4 nb = g_xyzT[(b << 16) + id];
        float rx = cc.x - nb.x, ry = cc.y - nb.y, rz = cc.z - nb.z;
        float dis = sqrtf(rx*rx + ry*ry + rz*rz);
        A[0] += dis;       A[1] += dis*dis;
        A[2] += dis*cc.x;  A[3] += dis*cc.y;  A[4] += dis*cc.z;
        A[5] += dis*nb.x;  A[6] += dis*nb.y;  A[7] += dis*nb.z;
        A[8] += cc.x;  A[9] += cc.y;  A[10] += cc.z;
        A[11] += nb.x; A[12] += nb.y; A[13] += nb.z;
        A[14] += cc.x*cc.x; A[15] += cc.x*cc.y; A[16] += cc.x*cc.z;
        A[17] += cc.y*cc.y; A[18] += cc.y*cc.z; A[19] += cc.z*cc.z;
        A[20] += nb.x*nb.x; A[21] += nb.x*nb.y; A[22] += nb.x*nb.z;
        A[23] += nb.y*nb.y; A[24] += nb.y*nb.z; A[25] += nb.z*nb.z;
        A[26] += nb.x*cc.x; A[27] += nb.x*cc.y; A[28] += nb.x*cc.z;
        A[29] += nb.y*cc.x; A[30] += nb.y*cc.y; A[31] += nb.y*cc.z;
        A[32] += nb.z*cc.x; A[33] += nb.z*cc.y; A[34] += nb.z*cc.z;
    }
    __shared__ float red[35];
    if (t < 35) red[t] = 0.f;
    __syncthreads();
    int lane = t & 31;
    #pragma unroll
    for (int i = 0; i < 35; i++){
        float v = wsum(A[i]);
        if (lane == 0) atomicAdd(&red[i], v);
    }
    __syncthreads();
    if (t < 35) atomicAdd(&g_acc[t], red[t]);
}

__device__ __forceinline__ int s6(int i, int j){
    if (i > j){ int x = i; i = j; j = x; }
    return i * 3 - ((i * (i + 1)) >> 1) + j;
}

// ---------------- finalize BN1 from moments ----------------
__global__ void k_fin1(const float* __restrict__ w1, const float* __restrict__ b1,
                       const float* __restrict__ g, const float* __restrict__ be){
    __shared__ float S10[10], M10[100];
    int t = threadIdx.x;
    if (t == 0){
        float A[35];
        for (int i = 0; i < 35; i++) A[i] = g_acc[i];
        const float* Adc = A + 2; const float* Adn = A + 5;
        const float* Ac  = A + 8; const float* An  = A + 11;
        const float* Acc = A + 14; const float* Ann = A + 20; const float* Anc = A + 26;
        S10[0] = A[0];
        for (int i = 0; i < 3; i++){
            S10[1+i] = Ac[i] - An[i]; S10[4+i] = Ac[i]; S10[7+i] = An[i];
        }
        float M[10][10];
        M[0][0] = A[1];
        for (int i = 0; i < 3; i++){
            M[0][1+i] = Adc[i] - Adn[i];
            M[0][4+i] = Adc[i];
            M[0][7+i] = Adn[i];
        }
        for (int i = 0; i < 3; i++) for (int j = 0; j < 3; j++){
            float cc = Acc[s6(i,j)], nn = Ann[s6(i,j)];
            float nicj = Anc[i*3+j];
            float njci = Anc[j*3+i];
            M[1+i][1+j] = cc - nicj - njci + nn;
            M[1+i][4+j] = cc - nicj;
            M[1+i][7+j] = njci - nn;
            M[4+i][4+j] = cc;
            M[4+i][7+j] = njci;
            M[7+i][7+j] = nn;
        }
        for (int i = 0; i < 10; i++) for (int j = 0; j < i; j++) M[i][j] = M[j][i];
        for (int i = 0; i < 10; i++) for (int j = 0; j < 10; j++) M10[i*10+j] = M[i][j];
    }
    __syncthreads();
    if (t < 16){
        float w[10];
        #pragma unroll
        for (int j = 0; j < 10; j++) w[j] = w1[t*10+j];
        float b = b1[t];
        float sw = 0.f;
        #pragma unroll
        for (int j = 0; j < 10; j++) sw += w[j] * S10[j];
        float q = 0.f;
        for (int i = 0; i < 10; i++){
            float wi = w[i];
            for (int j = 0; j < 10; j++) q += wi * w[j] * M10[i*10+j];
        }
        const float inv = 1.f / (float)NK;
        float mean = sw * inv + b;
        float ey2 = (q + 2.f * b * sw) * inv + b * b;
        float var = ey2 - mean * mean;
        float sc = g[t] * rsqrtf(var + EPSV);
        g_bnp[t] = sc;
        g_bnp[16 + t] = be[t] - mean * sc;
    }
}

// softmax helper: tree max + dual-acc sum/agg over 16 att values reading f from SMEM row base
__device__ __forceinline__ float softmax_agg(const float att[16], const float* fcol){
    // pairwise max tree (depth 4)
    float m0 = fmaxf(att[0], att[1]),   m1 = fmaxf(att[2], att[3]);
    float m2 = fmaxf(att[4], att[5]),   m3 = fmaxf(att[6], att[7]);
    float m4 = fmaxf(att[8], att[9]),   m5 = fmaxf(att[10], att[11]);
    float m6 = fmaxf(att[12], att[13]), m7 = fmaxf(att[14], att[15]);
    m0 = fmaxf(m0, m1); m2 = fmaxf(m2, m3); m4 = fmaxf(m4, m5); m6 = fmaxf(m6, m7);
    m0 = fmaxf(m0, m2); m4 = fmaxf(m4, m6);
    float m = fmaxf(m0, m4);
    float s0 = 0.f, s1 = 0.f, a0 = 0.f, a1 = 0.f;
    #pragma unroll
    for (int k = 0; k < 16; k += 2){
        float e0 = __expf(att[k] - m);
        float e1 = __expf(att[k + 1] - m);
        s0 += e0; s1 += e1;
        a0 += fcol[k * 32] * e0;
        a1 += fcol[(k + 1) * 32] * e1;
    }
    return (a0 + a1) / (s0 + s1);
}

// ---------------- stage 1: pool1 + all-lane y2 stats + z1 stats ----------------
__global__ void __launch_bounds__(256, 4) k_stage1(
        const int* __restrict__ nidx, const float* __restrict__ w1, const float* __restrict__ b1,
        const float* __restrict__ w2, const float* __restrict__ b2,
        const float* __restrict__ wfc, const float* __restrict__ bfc,
        const float* __restrict__ wap, const float* __restrict__ bap){
    __shared__ float W1s[160], b1s[16], sc1[16], sh1[16], b2s[16], baps[16];
    __shared__ __align__(16) float W2s[256];
    __shared__ __align__(16) float WapT[32*16];
    __shared__ __align__(16) float fS[8][16][32];
    __shared__ __align__(16) float aggS[8][32];
    __shared__ float red[64];
    int t = threadIdx.x;
    if (t < 160) W1s[t] = w1[t];
    if (t < 256) W2s[t] = w2[t];
    if (t < 16){ b1s[t]=b1[t]; b2s[t]=b2[t]; sc1[t]=g_bnp[t]; sh1[t]=g_bnp[16+t]; baps[t]=bap[t]; }
    for (int i = t; i < 512; i += 256){ int o = i >> 5, c = i & 31; WapT[c * 16 + o] = wap[i]; }
    __syncthreads();
    int lane = t & 31, w = t >> 5, c2 = lane - 16;
    int cL = lane & 15, h = lane >> 4;
    u64 wr2[16];
    #pragma unroll
    for (int j = 0; j < 16; j++) wr2[j] = pack2(wfc[lane * 32 + 2*j], wfc[lane * 32 + 2*j + 1]);
    float bfcl = bfc[lane];
    u64 w2r[8];
    {
        const ulonglong2* wpp = reinterpret_cast<const ulonglong2*>(&W2s[cL * 16]);
        ulonglong2 q0 = wpp[0], q1 = wpp[1], q2 = wpp[2], q3 = wpp[3];
        w2r[0]=q0.x; w2r[1]=q0.y; w2r[2]=q1.x; w2r[3]=q1.y;
        w2r[4]=q2.x; w2r[5]=q2.y; w2r[6]=q3.x; w2r[7]=q3.y;
    }
    float b2l = b2s[cL];
    float sZ = 0.f, ssZ = 0.f, sY = 0.f, ssY = 0.f;
    int warpsTotal = (gridDim.x * blockDim.x) >> 5;
    for (int pid = blockIdx.x * 8 + w; pid < NP; pid += warpsTotal){
        int b = pid >> 16;
        int idxl = nidx[(pid << 4) + cL];
        if (lane < 16){
            #pragma unroll
            for (int k = 0; k < 16; k++){
                int id = __shfl_sync(0x0000ffffu, idxl, k);
                fS[w][k][lane] = g_featT[((b << 16) + id) * CH + lane];
            }
        } else {
            float4 cc = g_xyzT[pid];
            const float* wp = W1s + c2 * 10;
            float w0=wp[0],w1r=wp[1],w2r_=wp[2],w3=wp[3],w4=wp[4],
                  w5=wp[5],w6=wp[6],w7=wp[7],w8=wp[8],w9=wp[9];
            float base = b1s[c2] + w4*cc.x + w5*cc.y + w6*cc.z;
            float s1 = sc1[c2], h1 = sh1[c2];
            #pragma unroll
            for (int k = 0; k < 16; k++){
                int id = __shfl_sync(0xffff0000u, idxl, 16 + k);
                float4 nb = g_xyzT[(b << 16) + id];
                float rx = cc.x - nb.x, ry = cc.y - nb.y, rz = cc.z - nb.z;
                float dis = sqrtf(rx*rx + ry*ry + rz*rz);
                float y = base + w0*dis + w1r*rx + w2r_*ry + w3*rz
                        + w7*nb.x + w8*nb.y + w9*nb.z;
                fS[w][k][lane] = lrelu(y * s1 + h1);
            }
        }
        __syncwarp();
        float att[16];
        #pragma unroll
        for (int k = 0; k < 16; k++){
            const ulonglong2* fp = reinterpret_cast<const ulonglong2*>(&fS[w][k][0]);
            u64 acc0 = 0ULL, acc1 = 0ULL;
            #pragma unroll
            for (int i = 0; i < 4; i++){
                ulonglong2 ua = fp[i];
                ulonglong2 ub = fp[i + 4];
                fma2(acc0, ua.x, wr2[2*i]);     fma2(acc0, ua.y, wr2[2*i + 1]);
                fma2(acc1, ub.x, wr2[2*i + 8]); fma2(acc1, ub.y, wr2[2*i + 9]);
            }
            att[k] = lohi_sum(acc0) + lohi_sum(acc1) + bfcl;
        }
        float agg = softmax_agg(att, &fS[w][0][lane]);
        aggS[w][lane] = agg;
        __syncwarp();
        if (lane < 16){
            float zA = baps[lane], zB = 0.f;
            #pragma unroll
            for (int c = 0; c < 32; c += 2){
                zA += WapT[c * 16 + lane] * aggS[w][c];
                zB += WapT[(c + 1) * 16 + lane] * aggS[w][c + 1];
            }
            float z = zA + zB;
            g_z1[pid * CH + lane] = z;
            sZ += z; ssZ += z * z;
        }
        // all-lane y2 stats: lane handles outputs (k = 2*i + h, c = cL)
        #pragma unroll
        for (int i = 0; i < 8; i++){
            int k = 2 * i + h;
            const ulonglong2* xp = reinterpret_cast<const ulonglong2*>(&fS[w][k][16]);
            u64 acc0 = 0ULL, acc1 = 0ULL;
            ulonglong2 u0 = xp[0], u1 = xp[1], u2 = xp[2], u3 = xp[3];
            fma2(acc0, u0.x, w2r[0]); fma2(acc0, u0.y, w2r[1]);
            fma2(acc0, u1.x, w2r[2]); fma2(acc0, u1.y, w2r[3]);
            fma2(acc1, u2.x, w2r[4]); fma2(acc1, u2.y, w2r[5]);
            fma2(acc1, u3.x, w2r[6]); fma2(acc1, u3.y, w2r[7]);
            float y2 = lohi_sum(acc0) + lohi_sum(acc1) + b2l;
            sY += y2; ssY += y2 * y2;
        }
        __syncwarp();
    }
    // epilogue: [0:16) z1 sum, [16:32) z1 sumsq, [32:48) y2 sum, [48:64) y2 sumsq
    if (t < 64) red[t] = 0.f;
    __syncthreads();
    if (lane < 16){
        atomicAdd(&red[lane], sZ);
        atomicAdd(&red[16 + lane], ssZ);
    }
    atomicAdd(&red[32 + cL], sY);
    atomicAdd(&red[48 + cL], ssY);
    __syncthreads();
    if (t < 16){
        atomicAdd(&g_acc[96 + t], red[t]);        // z1 stats (BN ap1)
        atomicAdd(&g_acc[112 + t], red[16 + t]);
        atomicAdd(&g_acc[64 + t], red[32 + t]);   // y2 stats (BN2)
        atomicAdd(&g_acc[80 + t], red[48 + t]);
    }
}

// ---------------- finalize BN2 (count NK) + BN ap1 (count NP) ----------------
__global__ void k_fin2AB(const float* __restrict__ g2, const float* __restrict__ be2,
                         const float* __restrict__ gA, const float* __restrict__ beA){
    int t = threadIdx.x;
    if (t < 16){
        float inv = 1.f / (float)NK;
        float m = g_acc[64 + t] * inv;
        float v = g_acc[80 + t] * inv - m * m;
        float sc = g2[t] * rsqrtf(v + EPSV);
        g_bnp[32 + t] = sc;
        g_bnp[48 + t] = be2[t] - m * sc;
    } else if (t < 32){
        int c = t - 16;
        float inv = 1.f / (float)NP;
        float m = g_acc[96 + c] * inv;
        float v = g_acc[112 + c] * inv - m * m;
        float sc = gA[c] * rsqrtf(v + EPSV);
        g_bnp[64 + c] = sc;
        g_bnp[80 + c] = beA[c] - m * sc;
    }
}

// ---------------- stage 2: recompute fx1, all-lane y2, pool2, fused z2 stats ----------------
__global__ void __launch_bounds__(256, 4) k_stage2(
        const int* __restrict__ nidx, const float* __restrict__ w1, const float* __restrict__ b1,
        const float* __restrict__ w2, const float* __restrict__ b2,
        const float* __restrict__ wfc, const float* __restrict__ bfc,
        const float* __restrict__ wap, const float* __restrict__ bap){
    __shared__ float W1s[160], b1s[16], sc1[16], sh1[16], sc2[16], sh2[16],
                     scA[16], shA[16], b2s[16], baps[32];
    __shared__ __align__(16) float W2s[256];
    __shared__ __align__(16) float WapT[32*32];
    __shared__ __align__(16) float fS[8][16][32];
    __shared__ __align__(16) float fx1S[8][16][16];
    __shared__ __align__(16) float aggS[8][32];
    __shared__ float red[64];
    int t = threadIdx.x;
    if (t < 160) W1s[t] = w1[t];
    if (t < 256) W2s[t] = w2[t];
    if (t < 16){
        b1s[t]=b1[t]; b2s[t]=b2[t];
        sc1[t]=g_bnp[t];    sh1[t]=g_bnp[16+t];
        sc2[t]=g_bnp[32+t]; sh2[t]=g_bnp[48+t];
        scA[t]=g_bnp[64+t]; shA[t]=g_bnp[80+t];
    }
    if (t < 32) baps[t] = bap[t];
    for (int i = t; i < 1024; i += 256){ int o = i >> 5, c = i & 31; WapT[c * 32 + o] = wap[i]; }
    __syncthreads();
    int lane = t & 31, w = t >> 5, c2 = lane - 16;
    int cL = lane & 15, h = lane >> 4;
    u64 wr2[16];
    #pragma unroll
    for (int j = 0; j < 16; j++) wr2[j] = pack2(wfc[lane * 32 + 2*j], wfc[lane * 32 + 2*j + 1]);
    float bfcl = bfc[lane];
    u64 w2r[8];
    {
        const ulonglong2* wpp = reinterpret_cast<const ulonglong2*>(&W2s[cL * 16]);
        ulonglong2 q0 = wpp[0], q1 = wpp[1], q2 = wpp[2], q3 = wpp[3];
        w2r[0]=q0.x; w2r[1]=q0.y; w2r[2]=q1.x; w2r[3]=q1.y;
        w2r[4]=q2.x; w2r[5]=q2.y; w2r[6]=q3.x; w2r[7]=q3.y;
    }
    float b2l = b2s[cL], s2l = sc2[cL], h2l = sh2[cL];
    float sA = 0.f, ssA = 0.f;
    int warpsTotal = (gridDim.x * blockDim.x) >> 5;
    for (int pid = blockIdx.x * 8 + w; pid < NP; pid += warpsTotal){
        int b = pid >> 16;
        int idxl = nidx[(pid << 4) + cL];
        if (lane < 16){
            float sa = scA[lane], ha = shA[lane];
            #pragma unroll
            for (int k = 0; k < 16; k++){
                int id = __shfl_sync(0x0000ffffu, idxl, k);
                float z = g_z1[((b << 16) + id) * CH + lane];
                fS[w][k][lane] = lrelu(z * sa + ha);
            }
        } else {
            float4 cc = g_xyzT[pid];
            const float* wp = W1s + c2 * 10;
            float w0=wp[0],w1r=wp[1],w2r_=wp[2],w3=wp[3],w4=wp[4],
                  w5=wp[5],w6=wp[6],w7=wp[7],w8=wp[8],w9=wp[9];
            float base = b1s[c2] + w4*cc.x + w5*cc.y + w6*cc.z;
            float s1 = sc1[c2], h1 = sh1[c2];
            #pragma unroll
            for (int k = 0; k < 16; k++){
                int id = __shfl_sync(0xffff0000u, idxl, 16 + k);
                float4 nb = g_xyzT[(b << 16) + id];
                float rx = cc.x - nb.x, ry = cc.y - nb.y, rz = cc.z - nb.z;
                float dis = sqrtf(rx*rx + ry*ry + rz*rz);
                float y = base + w0*dis + w1r*rx + w2r_*ry + w3*rz
                        + w7*nb.x + w8*nb.y + w9*nb.z;
                fx1S[w][k][c2] = lrelu(y * s1 + h1);
            }
        }
        __syncwarp();
        // all-lane y2: lane handles outputs (k = 2*i + h, c = cL); writes f into fS
        #pragma unroll
        for (int i = 0; i < 8; i++){
            int k = 2 * i + h;
            const ulonglong2* xp = reinterpret_cast<const ulonglong2*>(&fx1S[w][k][0]);
            u64 acc0 = 0ULL, acc1 = 0ULL;
            ulonglong2 u0 = xp[0], u1 = xp[1], u2 = xp[2], u3 = xp[3];
            fma2(acc0, u0.x, w2r[0]); fma2(acc0, u0.y, w2r[1]);
            fma2(acc0, u1.x, w2r[2]); fma2(acc0, u1.y, w2r[3]);
            fma2(acc1, u2.x, w2r[4]); fma2(acc1, u2.y, w2r[5]);
            fma2(acc1, u3.x, w2r[6]); fma2(acc1, u3.y, w2r[7]);
            float y2 = lohi_sum(acc0) + lohi_sum(acc1) + b2l;
            fS[w][k][16 + cL] = lrelu(y2 * s2l + h2l);
        }
        __syncwarp();
        float att[16];
        #pragma unroll
        for (int k = 0; k < 16; k++){
            const ulonglong2* fp = reinterpret_cast<const ulonglong2*>(&fS[w][k][0]);
            u64 acc0 = 0ULL, acc1 = 0ULL;
            #pragma unroll
            for (int i = 0; i < 4; i++){
                ulonglong2 ua = fp[i];
                ulonglong2 ub = fp[i + 4];
                fma2(acc0, ua.x, wr2[2*i]);     fma2(acc0, ua.y, wr2[2*i + 1]);
                fma2(acc1, ub.x, wr2[2*i + 8]); fma2(acc1, ub.y, wr2[2*i + 9]);
            }
            att[k] = lohi_sum(acc0) + lohi_sum(acc1) + bfcl;
        }
        float agg = softmax_agg(att, &fS[w][0][lane]);
        aggS[w][lane] = agg;
        __syncwarp();
        float zA = baps[lane], zB = 0.f;
        #pragma unroll
        for (int c = 0; c < 32; c += 2){
            zA += WapT[c * 32 + lane] * aggS[w][c];
            zB += WapT[(c + 1) * 32 + lane] * aggS[w][c + 1];
        }
        float z = zA + zB;
        g_z2[pid * CO + lane] = z;
        sA += z; ssA += z * z;
        __syncwarp();
    }
    if (t < 64) red[t] = 0.f;
    __syncthreads();
    atomicAdd(&red[lane], sA);
    atomicAdd(&red[32 + lane], ssA);
    __syncthreads();
    if (t < 32){
        atomicAdd(&g_acc[128 + t], red[t]);
        atomicAdd(&g_acc[160 + t], red[32 + t]);
    }
}

// ---------------- finalize BN ap2 ----------------
__global__ void k_finB(const float* __restrict__ g, const float* __restrict__ be){
    int t = threadIdx.x;
    if (t < 32){
        float inv = 1.f / (float)NP;
        float m = g_acc[128 + t] * inv;
        float v = g_acc[160 + t] * inv - m * m;
        float sc = g[t] * rsqrtf(v + EPSV);
        g_bnp[96 + t] = sc;
        g_bnp[128 + t] = be[t] - m * sc;
    }
}

// ---------------- final BN+LReLU + transpose to output layout ----------------
__global__ void k_out(float* __restrict__ out){
    __shared__ float tile[32][33];
    int bx = blockIdx.x;
    int b = bx >> 11;
    int n0 = (bx & 2047) << 5;
    int tx = threadIdx.x, ty = threadIdx.y;
    #pragma unroll
    for (int i = 0; i < 4; i++){
        int r = ty + i * 8;
        tile[r][tx] = g_z2[((b << 16) + n0 + r) * CO + tx];
    }
    __syncthreads();
    #pragma unroll
    for (int i = 0; i < 4; i++){
        int c = ty + i * 8;
        float v = tile[tx][c] * g_bnp[96 + c] + g_bnp[128 + c];
        out[(b * CO + c) * NPTS + n0 + tx] = lrelu(v);
    }
}

extern "C" void kernel_launch(void* const* d_in, const int* in_sizes, int n_in,
                              void* d_out, int out_size){
    const float* xyz     = (const float*)d_in[0];
    const float* feature = (const float*)d_in[1];
    const int*   nidx    = (const int*)  d_in[2];
    const float* w_mlp1  = (const float*)d_in[3];
    const float* b_mlp1  = (const float*)d_in[4];
    const float* g_mlp1  = (const float*)d_in[5];
    const float* be_mlp1 = (const float*)d_in[6];
    const float* w_fc1   = (const float*)d_in[7];
    const float* b_fc1   = (const float*)d_in[8];
    const float* w_ap1   = (const float*)d_in[9];
    const float* b_ap1   = (const float*)d_in[10];
    const float* g_ap1   = (const float*)d_in[11];
    const float* be_ap1  = (const float*)d_in[12];
    const float* w_mlp2  = (const float*)d_in[13];
    const float* b_mlp2  = (const float*)d_in[14];
    const float* g_mlp2  = (const float*)d_in[15];
    const float* be_mlp2 = (const float*)d_in[16];
    const float* w_fc2   = (const float*)d_in[17];
    const float* b_fc2   = (const float*)d_in[18];
    const float* w_ap2   = (const float*)d_in[19];
    const float* b_ap2   = (const float*)d_in[20];
    const float* g_ap2   = (const float*)d_in[21];
    const float* be_ap2  = (const float*)d_in[22];
    float* out = (float*)d_out;

    k_t01<<<512, 256>>>(xyz, feature);
    k_stats1e<<<512, 256>>>(nidx);
    k_fin1<<<1, 32>>>(w_mlp1, b_mlp1, g_mlp1, be_mlp1);
    k_stage1<<<SGRID, 256>>>(nidx, w_mlp1, b_mlp1, w_mlp2, b_mlp2, w_fc1, b_fc1, w_ap1, b_ap1);
    k_fin2AB<<<1, 32>>>(g_mlp2, be_mlp2, g_ap1, be_ap1);
    k_stage2<<<SGRID, 256>>>(nidx, w_mlp1, b_mlp1, w_mlp2, b_mlp2, w_fc2, b_fc2, w_ap2, b_ap2);
    k_finB<<<1, 32>>>(g_ap2, be_ap2);
    dim3 bt(32, 8);
    k_out<<<4096, bt>>>(out);
}

// round 17
// speedup vs baseline: 2.4850x; 1.0145x over previous
#include <cuda_runtime.h>

#define BS 2
#define NPTS 65536
#define KNN 16
#define CH 16
#define CO 32
#define NK (BS*NPTS*KNN)
#define NP (BS*NPTS)
#define EPSV 1e-5f
#define SLOPE 0.2f
#define SGRID 592   // 148 SMs x 4 blocks: single wave

// ---------------- scratch ----------------
__device__ float4 g_xyzT[NP];
__device__ float  g_featT[NP*CH];
__device__ float  g_z1[NP*CH];
__device__ float  g_z2[NP*CO];
__device__ float  g_acc[192];
__device__ float  g_bnp[192];

typedef unsigned long long u64;

__device__ __forceinline__ u64 pack2(float lo, float hi){
    u64 r; asm("mov.b64 %0, {%1,%2};" : "=l"(r) : "f"(lo), "f"(hi)); return r;
}
__device__ __forceinline__ void fma2(u64 &d, u64 a, u64 b){
    asm("fma.rn.f32x2 %0, %1, %2, %3;" : "=l"(d) : "l"(a), "l"(b), "l"(d));
}
__device__ __forceinline__ float lohi_sum(u64 v){
    float lo, hi; asm("mov.b64 {%0,%1}, %2;" : "=f"(lo), "=f"(hi) : "l"(v)); return lo + hi;
}
__device__ __forceinline__ float lrelu(float x){ return x >= 0.f ? x : SLOPE * x; }
__device__ __forceinline__ float wsum(float v){
    #pragma unroll
    for (int o = 16; o; o >>= 1) v += __shfl_down_sync(0xffffffffu, v, o);
    return v;
}

// ---------------- transpose xyz + feature, zero accumulators ----------------
__global__ void k_t01(const float* __restrict__ xyz, const float* __restrict__ feat){
    int i = blockIdx.x * blockDim.x + threadIdx.x;
    if (blockIdx.x == 0 && threadIdx.x < 192) g_acc[threadIdx.x] = 0.f;
    int b = i >> 16, n = i & 65535;
    const float* xp = xyz + b * 3 * NPTS;
    g_xyzT[i] = make_float4(xp[n], xp[NPTS + n], xp[2 * NPTS + n], 0.f);
    const float* fp = feat + b * CH * NPTS + n;
    float4* dst = reinterpret_cast<float4*>(&g_featT[i * CH]);
    #pragma unroll
    for (int q = 0; q < 4; q++){
        float4 v;
        v.x = fp[(4*q + 0) * NPTS];
        v.y = fp[(4*q + 1) * NPTS];
        v.z = fp[(4*q + 2) * NPTS];
        v.w = fp[(4*q + 3) * NPTS];
        dst[q] = v;
    }
}

// ---------------- per-edge raw moments for exact BN1 stats ----------------
__global__ void __launch_bounds__(256) k_stats1e(const int* __restrict__ nidx){
    float A[35];
    #pragma unroll
    for (int i = 0; i < 35; i++) A[i] = 0.f;
    int t = threadIdx.x;
    int T = gridDim.x * blockDim.x;
    for (int e = blockIdx.x * blockDim.x + t; e < NK; e += T){
        int id = nidx[e];
        int p = e >> 4, b = e >> 20;
        float4 cc = g_xyzT[p];
        float4 nb = g_xyzT[(b << 16) + id];
        float rx = cc.x - nb.x, ry = cc.y - nb.y, rz = cc.z - nb.z;
        float dis = sqrtf(rx*rx + ry*ry + rz*rz);
        A[0] += dis;       A[1] += dis*dis;
        A[2] += dis*cc.x;  A[3] += dis*cc.y;  A[4] += dis*cc.z;
        A[5] += dis*nb.x;  A[6] += dis*nb.y;  A[7] += dis*nb.z;
        A[8] += cc.x;  A[9] += cc.y;  A[10] += cc.z;
        A[11] += nb.x; A[12] += nb.y; A[13] += nb.z;
        A[14] += cc.x*cc.x; A[15] += cc.x*cc.y; A[16] += cc.x*cc.z;
        A[17] += cc.y*cc.y; A[18] += cc.y*cc.z; A[19] += cc.z*cc.z;
        A[20] += nb.x*nb.x; A[21] += nb.x*nb.y; A[22] += nb.x*nb.z;
        A[23] += nb.y*nb.y; A[24] += nb.y*nb.z; A[25] += nb.z*nb.z;
        A[26] += nb.x*cc.x; A[27] += nb.x*cc.y; A[28] += nb.x*cc.z;
        A[29] += nb.y*cc.x; A[30] += nb.y*cc.y; A[31] += nb.y*cc.z;
        A[32] += nb.z*cc.x; A[33] += nb.z*cc.y; A[34] += nb.z*cc.z;
    }
    __shared__ float red[35];
    if (t < 35) red[t] = 0.f;
    __syncthreads();
    int lane = t & 31;
    #pragma unroll
    for (int i = 0; i < 35; i++){
        float v = wsum(A[i]);
        if (lane == 0) atomicAdd(&red[i], v);
    }
    __syncthreads();
    if (t < 35) atomicAdd(&g_acc[t], red[t]);
}

__device__ __forceinline__ int s6(int i, int j){
    if (i > j){ int x = i; i = j; j = x; }
    return i * 3 - ((i * (i + 1)) >> 1) + j;
}

// ---------------- finalize BN1 from moments ----------------
__global__ void k_fin1(const float* __restrict__ w1, const float* __restrict__ b1,
                       const float* __restrict__ g, const float* __restrict__ be){
    __shared__ float S10[10], M10[100];
    int t = threadIdx.x;
    if (t == 0){
        float A[35];
        for (int i = 0; i < 35; i++) A[i] = g_acc[i];
        const float* Adc = A + 2; const float* Adn = A + 5;
        const float* Ac  = A + 8; const float* An  = A + 11;
        const float* Acc = A + 14; const float* Ann = A + 20; const float* Anc = A + 26;
        S10[0] = A[0];
        for (int i = 0; i < 3; i++){
            S10[1+i] = Ac[i] - An[i]; S10[4+i] = Ac[i]; S10[7+i] = An[i];
        }
        float M[10][10];
        M[0][0] = A[1];
        for (int i = 0; i < 3; i++){
            M[0][1+i] = Adc[i] - Adn[i];
            M[0][4+i] = Adc[i];
            M[0][7+i] = Adn[i];
        }
        for (int i = 0; i < 3; i++) for (int j = 0; j < 3; j++){
            float cc = Acc[s6(i,j)], nn = Ann[s6(i,j)];
            float nicj = Anc[i*3+j];
            float njci = Anc[j*3+i];
            M[1+i][1+j] = cc - nicj - njci + nn;
            M[1+i][4+j] = cc - nicj;
            M[1+i][7+j] = njci - nn;
            M[4+i][4+j] = cc;
            M[4+i][7+j] = njci;
            M[7+i][7+j] = nn;
        }
        for (int i = 0; i < 10; i++) for (int j = 0; j < i; j++) M[i][j] = M[j][i];
        for (int i = 0; i < 10; i++) for (int j = 0; j < 10; j++) M10[i*10+j] = M[i][j];
    }
    __syncthreads();
    if (t < 16){
        float w[10];
        #pragma unroll
        for (int j = 0; j < 10; j++) w[j] = w1[t*10+j];
        float b = b1[t];
        float sw = 0.f;
        #pragma unroll
        for (int j = 0; j < 10; j++) sw += w[j] * S10[j];
        float q = 0.f;
        for (int i = 0; i < 10; i++){
            float wi = w[i];
            for (int j = 0; j < 10; j++) q += wi * w[j] * M10[i*10+j];
        }
        const float inv = 1.f / (float)NK;
        float mean = sw * inv + b;
        float ey2 = (q + 2.f * b * sw) * inv + b * b;
        float var = ey2 - mean * mean;
        float sc = g[t] * rsqrtf(var + EPSV);
        g_bnp[t] = sc;
        g_bnp[16 + t] = be[t] - mean * sc;
    }
}

// softmax helper: tree max + dual-acc sum/agg
__device__ __forceinline__ float softmax_agg(const float att[16], const float* fcol){
    float m0 = fmaxf(att[0], att[1]),   m1 = fmaxf(att[2], att[3]);
    float m2 = fmaxf(att[4], att[5]),   m3 = fmaxf(att[6], att[7]);
    float m4 = fmaxf(att[8], att[9]),   m5 = fmaxf(att[10], att[11]);
    float m6 = fmaxf(att[12], att[13]), m7 = fmaxf(att[14], att[15]);
    m0 = fmaxf(m0, m1); m2 = fmaxf(m2, m3); m4 = fmaxf(m4, m5); m6 = fmaxf(m6, m7);
    m0 = fmaxf(m0, m2); m4 = fmaxf(m4, m6);
    float m = fmaxf(m0, m4);
    float s0 = 0.f, s1 = 0.f, a0 = 0.f, a1 = 0.f;
    #pragma unroll
    for (int k = 0; k < 16; k += 2){
        float e0 = __expf(att[k] - m);
        float e1 = __expf(att[k + 1] - m);
        s0 += e0; s1 += e1;
        a0 += fcol[k * 32] * e0;
        a1 += fcol[(k + 1) * 32] * e1;
    }
    return (a0 + a1) / (s0 + s1);
}

// ---------------- stage 1: pool1 + all-lane y2 stats + z1 stats ----------------
// BN1 folded into W1s/b1s. W2 kept RAW (stage1 computes BN2 stats). Wap pair-packed.
__global__ void __launch_bounds__(256, 4) k_stage1(
        const int* __restrict__ nidx, const float* __restrict__ w1, const float* __restrict__ b1,
        const float* __restrict__ w2, const float* __restrict__ b2,
        const float* __restrict__ wfc, const float* __restrict__ bfc,
        const float* __restrict__ wap, const float* __restrict__ bap){
    __shared__ float W1s[160], b1s[16], b2s[16], baps[16];
    __shared__ __align__(16) float W2s[256];
    __shared__ __align__(16) u64 WapP[16*16];     // [pair i][out o]
    __shared__ __align__(16) float fS[8][16][32];
    __shared__ __align__(16) float aggS[8][32];
    __shared__ float red[64];
    int t = threadIdx.x;
    if (t < 160) W1s[t] = w1[t] * g_bnp[t / 10];                 // BN1 scale folded
    if (t < 256) W2s[t] = w2[t];                                 // raw
    if (t < 16){
        b1s[t] = b1[t] * g_bnp[t] + g_bnp[16 + t];               // BN1 shift folded
        b2s[t] = b2[t];
        baps[t] = bap[t];
    }
    if (t < 256){ int i = t >> 4, o = t & 15;                    // 16 pairs x 16 outs
        WapP[i * 16 + o] = pack2(wap[o * 32 + 2*i], wap[o * 32 + 2*i + 1]);
    }
    __syncthreads();
    int lane = t & 31, w = t >> 5, c2 = lane - 16;
    int cL = lane & 15, h = lane >> 4;
    u64 wr2[16];
    #pragma unroll
    for (int j = 0; j < 16; j++) wr2[j] = pack2(wfc[lane * 32 + 2*j], wfc[lane * 32 + 2*j + 1]);
    float bfcl = bfc[lane];
    u64 w2r[8];
    {
        const ulonglong2* wpp = reinterpret_cast<const ulonglong2*>(&W2s[cL * 16]);
        ulonglong2 q0 = wpp[0], q1 = wpp[1], q2 = wpp[2], q3 = wpp[3];
        w2r[0]=q0.x; w2r[1]=q0.y; w2r[2]=q1.x; w2r[3]=q1.y;
        w2r[4]=q2.x; w2r[5]=q2.y; w2r[6]=q3.x; w2r[7]=q3.y;
    }
    float b2l = b2s[cL];
    float sZ = 0.f, ssZ = 0.f, sY = 0.f, ssY = 0.f;
    int warpsTotal = (gridDim.x * blockDim.x) >> 5;
    for (int pid = blockIdx.x * 8 + w; pid < NP; pid += warpsTotal){
        int b = pid >> 16;
        int idxl = nidx[(pid << 4) + cL];
        if (lane < 16){
            #pragma unroll
            for (int k = 0; k < 16; k++){
                int id = __shfl_sync(0x0000ffffu, idxl, k);
                fS[w][k][lane] = g_featT[((b << 16) + id) * CH + lane];
            }
        } else {
            float4 cc = g_xyzT[pid];
            const float* wp = W1s + c2 * 10;
            float w0=wp[0],w1r=wp[1],w2r_=wp[2],w3=wp[3],w4=wp[4],
                  w5=wp[5],w6=wp[6],w7=wp[7],w8=wp[8],w9=wp[9];
            float base = b1s[c2] + w4*cc.x + w5*cc.y + w6*cc.z;
            #pragma unroll
            for (int k = 0; k < 16; k++){
                int id = __shfl_sync(0xffff0000u, idxl, 16 + k);
                float4 nb = g_xyzT[(b << 16) + id];
                float rx = cc.x - nb.x, ry = cc.y - nb.y, rz = cc.z - nb.z;
                float dis = sqrtf(rx*rx + ry*ry + rz*rz);
                float y = base + w0*dis + w1r*rx + w2r_*ry + w3*rz
                        + w7*nb.x + w8*nb.y + w9*nb.z;
                fS[w][k][lane] = lrelu(y);
            }
        }
        __syncwarp();
        float att[16];
        #pragma unroll
        for (int k = 0; k < 16; k++){
            const ulonglong2* fp = reinterpret_cast<const ulonglong2*>(&fS[w][k][0]);
            u64 acc0 = 0ULL, acc1 = 0ULL;
            #pragma unroll
            for (int i = 0; i < 4; i++){
                ulonglong2 ua = fp[i];
                ulonglong2 ub = fp[i + 4];
                fma2(acc0, ua.x, wr2[2*i]);     fma2(acc0, ua.y, wr2[2*i + 1]);
                fma2(acc1, ub.x, wr2[2*i + 8]); fma2(acc1, ub.y, wr2[2*i + 9]);
            }
            att[k] = lohi_sum(acc0) + lohi_sum(acc1) + bfcl;
        }
        float agg = softmax_agg(att, &fS[w][0][lane]);
        aggS[w][lane] = agg;
        __syncwarp();
        if (lane < 16){
            const ulonglong2* ap = reinterpret_cast<const ulonglong2*>(&aggS[w][0]);
            u64 acc0 = 0ULL, acc1 = 0ULL;
            #pragma unroll
            for (int q = 0; q < 8; q++){
                ulonglong2 u = ap[q];
                fma2(acc0, u.x, WapP[(2*q)     * 16 + lane]);
                fma2(acc1, u.y, WapP[(2*q + 1) * 16 + lane]);
            }
            float z = lohi_sum(acc0) + lohi_sum(acc1) + baps[lane];
            g_z1[pid * CH + lane] = z;
            sZ += z; ssZ += z * z;
        }
        #pragma unroll
        for (int i = 0; i < 8; i++){
            int k = 2 * i + h;
            const ulonglong2* xp = reinterpret_cast<const ulonglong2*>(&fS[w][k][16]);
            u64 acc0 = 0ULL, acc1 = 0ULL;
            ulonglong2 u0 = xp[0], u1 = xp[1], u2 = xp[2], u3 = xp[3];
            fma2(acc0, u0.x, w2r[0]); fma2(acc0, u0.y, w2r[1]);
            fma2(acc0, u1.x, w2r[2]); fma2(acc0, u1.y, w2r[3]);
            fma2(acc1, u2.x, w2r[4]); fma2(acc1, u2.y, w2r[5]);
            fma2(acc1, u3.x, w2r[6]); fma2(acc1, u3.y, w2r[7]);
            float y2 = lohi_sum(acc0) + lohi_sum(acc1) + b2l;
            sY += y2; ssY += y2 * y2;
        }
        __syncwarp();
    }
    if (t < 64) red[t] = 0.f;
    __syncthreads();
    if (lane < 16){
        atomicAdd(&red[lane], sZ);
        atomicAdd(&red[16 + lane], ssZ);
    }
    atomicAdd(&red[32 + cL], sY);
    atomicAdd(&red[48 + cL], ssY);
    __syncthreads();
    if (t < 16){
        atomicAdd(&g_acc[96 + t], red[t]);
        atomicAdd(&g_acc[112 + t], red[16 + t]);
        atomicAdd(&g_acc[64 + t], red[32 + t]);
        atomicAdd(&g_acc[80 + t], red[48 + t]);
    }
}

// ---------------- finalize BN2 (count NK) + BN ap1 (count NP) ----------------
__global__ void k_fin2AB(const float* __restrict__ g2, const float* __restrict__ be2,
                         const float* __restrict__ gA, const float* __restrict__ beA){
    int t = threadIdx.x;
    if (t < 16){
        float inv = 1.f / (float)NK;
        float m = g_acc[64 + t] * inv;
        float v = g_acc[80 + t] * inv - m * m;
        float sc = g2[t] * rsqrtf(v + EPSV);
        g_bnp[32 + t] = sc;
        g_bnp[48 + t] = be2[t] - m * sc;
    } else if (t < 32){
        int c = t - 16;
        float inv = 1.f / (float)NP;
        float m = g_acc[96 + c] * inv;
        float v = g_acc[112 + c] * inv - m * m;
        float sc = gA[c] * rsqrtf(v + EPSV);
        g_bnp[64 + c] = sc;
        g_bnp[80 + c] = beA[c] - m * sc;
    }
}

// ---------------- stage 2: BN1+BN2 folded, pair-packed Wap ----------------
__global__ void __launch_bounds__(256, 4) k_stage2(
        const int* __restrict__ nidx, const float* __restrict__ w1, const float* __restrict__ b1,
        const float* __restrict__ w2, const float* __restrict__ b2,
        const float* __restrict__ wfc, const float* __restrict__ bfc,
        const float* __restrict__ wap, const float* __restrict__ bap){
    __shared__ float W1s[160], b1s[16], scA[16], shA[16], b2s[16], baps[32];
    __shared__ __align__(16) float W2s[256];
    __shared__ __align__(16) u64 WapP[16*32];     // [pair i][out o]
    __shared__ __align__(16) float fS[8][16][32];
    __shared__ __align__(16) float fx1S[8][16][16];
    __shared__ __align__(16) float aggS[8][32];
    __shared__ float red[64];
    int t = threadIdx.x;
    if (t < 160) W1s[t] = w1[t] * g_bnp[t / 10];                 // BN1 folded
    if (t < 256) W2s[t] = w2[t] * g_bnp[32 + (t >> 4)];          // BN2 folded (row t/16)
    if (t < 16){
        b1s[t] = b1[t] * g_bnp[t] + g_bnp[16 + t];
        b2s[t] = b2[t] * g_bnp[32 + t] + g_bnp[48 + t];
        scA[t] = g_bnp[64 + t]; shA[t] = g_bnp[80 + t];
    }
    if (t < 32) baps[t] = bap[t];
    for (int i0 = t; i0 < 512; i0 += 256){ int i = i0 >> 5, o = i0 & 31;
        WapP[i * 32 + o] = pack2(wap[o * 32 + 2*i], wap[o * 32 + 2*i + 1]);
    }
    __syncthreads();
    int lane = t & 31, w = t >> 5, c2 = lane - 16;
    int cL = lane & 15, h = lane >> 4;
    u64 wr2[16];
    #pragma unroll
    for (int j = 0; j < 16; j++) wr2[j] = pack2(wfc[lane * 32 + 2*j], wfc[lane * 32 + 2*j + 1]);
    float bfcl = bfc[lane];
    u64 w2r[8];
    {
        const ulonglong2* wpp = reinterpret_cast<const ulonglong2*>(&W2s[cL * 16]);
        ulonglong2 q0 = wpp[0], q1 = wpp[1], q2 = wpp[2], q3 = wpp[3];
        w2r[0]=q0.x; w2r[1]=q0.y; w2r[2]=q1.x; w2r[3]=q1.y;
        w2r[4]=q2.x; w2r[5]=q2.y; w2r[6]=q3.x; w2r[7]=q3.y;
    }
    float b2l = b2s[cL];
    float sA = 0.f, ssA = 0.f;
    int warpsTotal = (gridDim.x * blockDim.x) >> 5;
    for (int pid = blockIdx.x * 8 + w; pid < NP; pid += warpsTotal){
        int b = pid >> 16;
        int idxl = nidx[(pid << 4) + cL];
        if (lane < 16){
            float sa = scA[lane], ha = shA[lane];
            #pragma unroll
            for (int k = 0; k < 16; k++){
                int id = __shfl_sync(0x0000ffffu, idxl, k);
                float z = g_z1[((b << 16) + id) * CH + lane];
                fS[w][k][lane] = lrelu(z * sa + ha);
            }
        } else {
            float4 cc = g_xyzT[pid];
            const float* wp = W1s + c2 * 10;
            float w0=wp[0],w1r=wp[1],w2r_=wp[2],w3=wp[3],w4=wp[4],
                  w5=wp[5],w6=wp[6],w7=wp[7],w8=wp[8],w9=wp[9];
            float base = b1s[c2] + w4*cc.x + w5*cc.y + w6*cc.z;
            #pragma unroll
            for (int k = 0; k < 16; k++){
                int id = __shfl_sync(0xffff0000u, idxl, 16 + k);
                float4 nb = g_xyzT[(b << 16) + id];
                float rx = cc.x - nb.x, ry = cc.y - nb.y, rz = cc.z - nb.z;
                float dis = sqrtf(rx*rx + ry*ry + rz*rz);
                float y = base + w0*dis + w1r*rx + w2r_*ry + w3*rz
                        + w7*nb.x + w8*nb.y + w9*nb.z;
                fx1S[w][k][c2] = lrelu(y);
            }
        }
        __syncwarp();
        #pragma unroll
        for (int i = 0; i < 8; i++){
            int k = 2 * i + h;
            const ulonglong2* xp = reinterpret_cast<const ulonglong2*>(&fx1S[w][k][0]);
            u64 acc0 = 0ULL, acc1 = 0ULL;
            ulonglong2 u0 = xp[0], u1 = xp[1], u2 = xp[2], u3 = xp[3];
            fma2(acc0, u0.x, w2r[0]); fma2(acc0, u0.y, w2r[1]);
            fma2(acc0, u1.x, w2r[2]); fma2(acc0, u1.y, w2r[3]);
            fma2(acc1, u2.x, w2r[4]); fma2(acc1, u2.y, w2r[5]);
            fma2(acc1, u3.x, w2r[6]); fma2(acc1, u3.y, w2r[7]);
            float y2 = lohi_sum(acc0) + lohi_sum(acc1) + b2l;
            fS[w][k][16 + cL] = lrelu(y2);
        }
        __syncwarp();
        float att[16];
        #pragma unroll
        for (int k = 0; k < 16; k++){
            const ulonglong2* fp = reinterpret_cast<const ulonglong2*>(&fS[w][k][0]);
            u64 acc0 = 0ULL, acc1 = 0ULL;
            #pragma unroll
            for (int i = 0; i < 4; i++){
                ulonglong2 ua = fp[i];
                ulonglong2 ub = fp[i + 4];
                fma2(acc0, ua.x, wr2[2*i]);     fma2(acc0, ua.y, wr2[2*i + 1]);
                fma2(acc1, ub.x, wr2[2*i + 8]); fma2(acc1, ub.y, wr2[2*i + 9]);
            }
            att[k] = lohi_sum(acc0) + lohi_sum(acc1) + bfcl;
        }
        float agg = softmax_agg(att, &fS[w][0][lane]);
        aggS[w][lane] = agg;
        __syncwarp();
        {
            const ulonglong2* ap = reinterpret_cast<const ulonglong2*>(&aggS[w][0]);
            u64 acc0 = 0ULL, acc1 = 0ULL;
            #pragma unroll
            for (int q = 0; q < 8; q++){
                ulonglong2 u = ap[q];
                fma2(acc0, u.x, WapP[(2*q)     * 32 + lane]);
                fma2(acc1, u.y, WapP[(2*q + 1) * 32 + lane]);
            }
            float z = lohi_sum(acc0) + lohi_sum(acc1) + baps[lane];
            g_z2[pid * CO + lane] = z;
            sA += z; ssA += z * z;
        }
        __syncwarp();
    }
    if (t < 64) red[t] = 0.f;
    __syncthreads();
    atomicAdd(&red[lane], sA);
    atomicAdd(&red[32 + lane], ssA);
    __syncthreads();
    if (t < 32){
        atomicAdd(&g_acc[128 + t], red[t]);
        atomicAdd(&g_acc[160 + t], red[32 + t]);
    }
}

// ---------------- finalize BN ap2 ----------------
__global__ void k_finB(const float* __restrict__ g, const float* __restrict__ be){
    int t = threadIdx.x;
    if (t < 32){
        float inv = 1.f / (float)NP;
        float m = g_acc[128 + t] * inv;
        float v = g_acc[160 + t] * inv - m * m;
        float sc = g[t] * rsqrtf(v + EPSV);
        g_bnp[96 + t] = sc;
        g_bnp[128 + t] = be[t] - m * sc;
    }
}

// ---------------- final BN+LReLU + transpose to output layout ----------------
__global__ void k_out(float* __restrict__ out){
    __shared__ float tile[32][33];
    int bx = blockIdx.x;
    int b = bx >> 11;
    int n0 = (bx & 2047) << 5;
    int tx = threadIdx.x, ty = threadIdx.y;
    #pragma unroll
    for (int i = 0; i < 4; i++){
        int r = ty + i * 8;
        tile[r][tx] = g_z2[((b << 16) + n0 + r) * CO + tx];
    }
    __syncthreads();
    #pragma unroll
    for (int i = 0; i < 4; i++){
        int c = ty + i * 8;
        float v = tile[tx][c] * g_bnp[96 + c] + g_bnp[128 + c];
        out[(b * CO + c) * NPTS + n0 + tx] = lrelu(v);
    }
}

extern "C" void kernel_launch(void* const* d_in, const int* in_sizes, int n_in,
                              void* d_out, int out_size){
    const float* xyz     = (const float*)d_in[0];
    const float* feature = (const float*)d_in[1];
    const int*   nidx    = (const int*)  d_in[2];
    const float* w_mlp1  = (const float*)d_in[3];
    const float* b_mlp1  = (const float*)d_in[4];
    const float* g_mlp1  = (const float*)d_in[5];
    const float* be_mlp1 = (const float*)d_in[6];
    const float* w_fc1   = (const float*)d_in[7];
    const float* b_fc1   = (const float*)d_in[8];
    const float* w_ap1   = (const float*)d_in[9];
    const float* b_ap1   = (const float*)d_in[10];
    const float* g_ap1   = (const float*)d_in[11];
    const float* be_ap1  = (const float*)d_in[12];
    const float* w_mlp2  = (const float*)d_in[13];
    const float* b_mlp2  = (const float*)d_in[14];
    const float* g_mlp2  = (const float*)d_in[15];
    const float* be_mlp2 = (const float*)d_in[16];
    const float* w_fc2   = (const float*)d_in[17];
    const float* b_fc2   = (const float*)d_in[18];
    const float* w_ap2   = (const float*)d_in[19];
    const float* b_ap2   = (const float*)d_in[20];
    const float* g_ap2   = (const float*)d_in[21];
    const float* be_ap2  = (const float*)d_in[22];
    float* out = (float*)d_out;

    k_t01<<<512, 256>>>(xyz, feature);
    k_stats1e<<<512, 256>>>(nidx);
    k_fin1<<<1, 32>>>(w_mlp1, b_mlp1, g_mlp1, be_mlp1);
    k_stage1<<<SGRID, 256>>>(nidx, w_mlp1, b_mlp1, w_mlp2, b_mlp2, w_fc1, b_fc1, w_ap1, b_ap1);
    k_fin2AB<<<1, 32>>>(g_mlp2, be_mlp2, g_ap1, be_ap1);
    k_stage2<<<SGRID, 256>>>(nidx, w_mlp1, b_mlp1, w_mlp2, b_mlp2, w_fc2, b_fc2, w_ap2, b_ap2);
    k_finB<<<1, 32>>>(g_ap2, be_ap2);
    dim3 bt(32, 8);
    k_out<<<4096, bt>>>(out);
}